// round 6
// baseline (speedup 1.0000x reference)
#include <cuda_runtime.h>
#include <cuda_bf16.h>
#include <cstdint>

#define BB   4
#define SS   2048
#define HH   1024
#define NHH  16
#define HDD  64
#define MM   (BB*SS)      // 8192
#define N3   (3*HH)       // 3072
#define KK   1024
#define STR  40           // smem row stride in bf16 (80B -> conflict-free ldmatrix)

typedef unsigned long long ull;

// ---------------- packed f32x2 helpers (attention kernel) ----------------
__device__ __forceinline__ ull ffma2(ull a, ull b, ull c) {
    ull d;
    asm("fma.rn.f32x2 %0, %1, %2, %3;" : "=l"(d) : "l"(a), "l"(b), "l"(c));
    return d;
}
__device__ __forceinline__ ull fmul2(ull a, ull b) {
    ull d;
    asm("mul.rn.f32x2 %0, %1, %2;" : "=l"(d) : "l"(a), "l"(b));
    return d;
}
__device__ __forceinline__ ull pack2(float x) {
    ull r;
    asm("mov.b64 %0, {%1, %1};" : "=l"(r) : "f"(x));
    return r;
}
__device__ __forceinline__ float2 unpack2(ull v) {
    float2 r;
    asm("mov.b64 {%0, %1}, %2;" : "=f"(r.x), "=f"(r.y) : "l"(v));
    return r;
}

// ---------------- tensor-core helpers (arch-portable mma.sync path) ----------------
__device__ __forceinline__ uint32_t smem_u32(const void* p) {
    uint32_t a;
    asm("{ .reg .u64 t; cvta.to.shared.u64 t, %1; cvt.u32.u64 %0, t; }" : "=r"(a) : "l"(p));
    return a;
}
__device__ __forceinline__ void ldsm4(uint32_t* r, uint32_t addr) {
    asm volatile("ldmatrix.sync.aligned.m8n8.x4.shared.b16 {%0,%1,%2,%3}, [%4];"
        : "=r"(r[0]), "=r"(r[1]), "=r"(r[2]), "=r"(r[3]) : "r"(addr));
}
__device__ __forceinline__ void mma16816(float* c, const uint32_t* a, const uint32_t* b) {
    asm volatile("mma.sync.aligned.m16n8k16.row.col.f32.bf16.bf16.f32 "
        "{%0,%1,%2,%3}, {%4,%5,%6,%7}, {%8,%9}, {%0,%1,%2,%3};"
        : "+f"(c[0]), "+f"(c[1]), "+f"(c[2]), "+f"(c[3])
        : "r"(a[0]), "r"(a[1]), "r"(a[2]), "r"(a[3]), "r"(b[0]), "r"(b[1]));
}

// ---------------- scratch (__device__ globals; no runtime alloc) ----------------
__device__ __align__(128) __nv_bfloat16 g_xh[(size_t)MM * KK];     // LN out hi
__device__ __align__(128) __nv_bfloat16 g_xl[(size_t)MM * KK];     // LN out lo
__device__ __align__(128) __nv_bfloat16 g_wqh[(size_t)N3 * KK];    // qkv W^T hi [3072,1024]
__device__ __align__(128) __nv_bfloat16 g_wql[(size_t)N3 * KK];
__device__ __align__(128) __nv_bfloat16 g_wph[(size_t)HH * KK];    // proj W^T hi [1024,1024]
__device__ __align__(128) __nv_bfloat16 g_wpl[(size_t)HH * KK];
__device__ __align__(128) __nv_bfloat16 g_ch[(size_t)MM * HH];     // ctx hi
__device__ __align__(128) __nv_bfloat16 g_cl[(size_t)MM * HH];     // ctx lo
__device__ float g_q[(size_t)BB * NHH * SS * HDD];                 // [b,h,s,d]
__device__ float g_k[(size_t)BB * NHH * SS * HDD];
__device__ float g_v[(size_t)BB * NHH * SS * HDD];

// ---------------- layernorm + bf16 hi/lo split ----------------
__global__ __launch_bounds__(256) void ln_kernel(const float* __restrict__ hs,
                                                 const float* __restrict__ gamma,
                                                 const float* __restrict__ beta) {
    const int row = blockIdx.x;
    const int tid = threadIdx.x;
    const float4 v = ((const float4*)(hs + (size_t)row * HH))[tid];
    float s  = v.x + v.y + v.z + v.w;
    float s2 = v.x*v.x + v.y*v.y + v.z*v.z + v.w*v.w;
    #pragma unroll
    for (int o = 16; o > 0; o >>= 1) {
        s  += __shfl_xor_sync(0xffffffffu, s,  o);
        s2 += __shfl_xor_sync(0xffffffffu, s2, o);
    }
    __shared__ float red[2][8];
    const int wid = tid >> 5, lane = tid & 31;
    if (lane == 0) { red[0][wid] = s; red[1][wid] = s2; }
    __syncthreads();
    float mean = 0.f, msq = 0.f;
    #pragma unroll
    for (int i = 0; i < 8; i++) { mean += red[0][i]; msq += red[1][i]; }
    mean *= (1.0f / HH);
    msq  *= (1.0f / HH);
    const float rstd = rsqrtf(msq - mean * mean + 1e-5f);
    const float4 g = ((const float4*)gamma)[tid];
    const float4 b = ((const float4*)beta)[tid];
    float o[4];
    o[0] = (v.x - mean) * rstd * g.x + b.x;
    o[1] = (v.y - mean) * rstd * g.y + b.y;
    o[2] = (v.z - mean) * rstd * g.z + b.z;
    o[3] = (v.w - mean) * rstd * g.w + b.w;
    __nv_bfloat16 h[4], l[4];
    #pragma unroll
    for (int i = 0; i < 4; i++) {
        h[i] = __float2bfloat16(o[i]);
        l[i] = __float2bfloat16(o[i] - __bfloat162float(h[i]));
    }
    const size_t off = (size_t)row * HH + tid * 4;
    *(__nv_bfloat162*)(g_xh + off)     = __nv_bfloat162(h[0], h[1]);
    *(__nv_bfloat162*)(g_xh + off + 2) = __nv_bfloat162(h[2], h[3]);
    *(__nv_bfloat162*)(g_xl + off)     = __nv_bfloat162(l[0], l[1]);
    *(__nv_bfloat162*)(g_xl + off + 2) = __nv_bfloat162(l[2], l[3]);
}

// ---------------- weight transpose + split: W[K=1024, N] -> WT_h/WT_l [N, 1024] ----
__global__ __launch_bounds__(256) void wsplit_kernel(const float* __restrict__ W,
                                                     __nv_bfloat16* __restrict__ Th,
                                                     __nv_bfloat16* __restrict__ Tl,
                                                     int N) {
    __shared__ float sm[32][33];
    const int n0 = blockIdx.x * 32, k0 = blockIdx.y * 32;
    const int tx = threadIdx.x & 31, ty = threadIdx.x >> 5;
    #pragma unroll
    for (int i = 0; i < 4; i++) {
        const int k = ty * 4 + i;
        sm[k][tx] = W[(size_t)(k0 + k) * N + n0 + tx];
    }
    __syncthreads();
    #pragma unroll
    for (int i = 0; i < 4; i++) {
        const int n = ty * 4 + i;
        const float v = sm[tx][n];
        const __nv_bfloat16 h = __float2bfloat16(v);
        const __nv_bfloat16 l = __float2bfloat16(v - __bfloat162float(h));
        Th[(size_t)(n0 + n) * KK + k0 + tx] = h;
        Tl[(size_t)(n0 + n) * KK + k0 + tx] = l;
    }
}

// ---------------- split-bf16 mma.sync GEMM: C[128x128] = A[M,K] @ B[N,K]^T ----------
// EPI 0: qkv bias+scatter into g_q/g_k/g_v.  EPI 1: out = acc + bias + resid.
#define MMA_SMEM (8 * 128 * STR * 2)   // 4 operands x 2 buffers x 128 x STR bf16
template<int EPI>
__global__ __launch_bounds__(256) void mma_gemm_kernel(
    const __nv_bfloat16* __restrict__ Ah, const __nv_bfloat16* __restrict__ Al,
    const __nv_bfloat16* __restrict__ Bh, const __nv_bfloat16* __restrict__ Bl,
    const float* __restrict__ bias, const float* __restrict__ resid,
    float* __restrict__ outp)
{
    extern __shared__ __nv_bfloat16 smb[];
    const int tid = threadIdx.x, wid = tid >> 5, lane = tid & 31;
    const int bm = blockIdx.y, bn = blockIdx.x;
    const int wm = wid >> 2, wn = wid & 3;
    const uint32_t sbase = smem_u32(smb);

    const __nv_bfloat16* gA0 = Ah + (size_t)bm * 128 * KK;
    const __nv_bfloat16* gA1 = Al + (size_t)bm * 128 * KK;
    const __nv_bfloat16* gB0 = Bh + (size_t)bn * 128 * KK;
    const __nv_bfloat16* gB1 = Bl + (size_t)bn * 128 * KK;

    float c[4][4][4];
    #pragma unroll
    for (int i = 0; i < 4; i++)
        #pragma unroll
        for (int j = 0; j < 4; j++)
            #pragma unroll
            for (int q = 0; q < 4; q++) c[i][j][q] = 0.f;

    const int lrow = tid >> 2;   // 0..63, second half +64
    const int lseg = tid & 3;

    uint4 pre[4][2];
    auto gload = [&](int k0) {
        #pragma unroll
        for (int op = 0; op < 4; op++) {
            const __nv_bfloat16* src = (op == 0) ? gA0 : (op == 1) ? gA1 : (op == 2) ? gB0 : gB1;
            #pragma unroll
            for (int i = 0; i < 2; i++) {
                const int row = lrow + i * 64;
                pre[op][i] = *(const uint4*)(src + (size_t)row * KK + k0 + lseg * 8);
            }
        }
    };
    auto s2s = [&](int buf) {
        #pragma unroll
        for (int op = 0; op < 4; op++)
            #pragma unroll
            for (int i = 0; i < 2; i++) {
                const int row = lrow + i * 64;
                *(uint4*)(smb + (size_t)(buf * 4 + op) * 128 * STR + row * STR + lseg * 8) = pre[op][i];
            }
    };

    gload(0);
    s2s(0);
    __syncthreads();

    // ldmatrix per-lane addressing
    const int a_r = lane & 15;
    const int a_c = (lane >> 4) * 8;
    const int b_r = ((lane >> 4) << 3) + (lane & 7);
    const int b_c = ((lane >> 3) & 1) * 8;

    const int NCH = KK / 32;  // 32
    for (int ch = 0; ch < NCH; ch++) {
        const int buf = ch & 1;
        if (ch + 1 < NCH) gload((ch + 1) * 32);
        #pragma unroll
        for (int pass = 0; pass < 3; pass++) {
            const int aop = (pass == 2) ? 1 : 0;
            const int bop = (pass == 1) ? 3 : 2;
            const uint32_t abase = sbase + (uint32_t)((buf * 4 + aop) * 128 * STR) * 2;
            const uint32_t bbase = sbase + (uint32_t)((buf * 4 + bop) * 128 * STR) * 2;
            #pragma unroll
            for (int ks = 0; ks < 2; ks++) {
                uint32_t a[4][4], b[2][4];
                #pragma unroll
                for (int mi = 0; mi < 4; mi++)
                    ldsm4(a[mi], abase + (uint32_t)((wm * 64 + mi * 16 + a_r) * STR + ks * 16 + a_c) * 2);
                #pragma unroll
                for (int pj = 0; pj < 2; pj++)
                    ldsm4(b[pj], bbase + (uint32_t)((wn * 32 + pj * 16 + b_r) * STR + ks * 16 + b_c) * 2);
                #pragma unroll
                for (int mi = 0; mi < 4; mi++)
                    #pragma unroll
                    for (int nj = 0; nj < 4; nj++)
                        mma16816(c[mi][nj], a[mi], &b[nj >> 1][(nj & 1) * 2]);
            }
        }
        if (ch + 1 < NCH) s2s(1 - buf);
        __syncthreads();
    }

    // epilogue
    #pragma unroll
    for (int mi = 0; mi < 4; mi++) {
        #pragma unroll
        for (int half = 0; half < 2; half++) {
            const int r = bm * 128 + wm * 64 + mi * 16 + (lane >> 2) + half * 8;
            #pragma unroll
            for (int nj = 0; nj < 4; nj++) {
                const int n = bn * 128 + wn * 32 + nj * 8 + (lane & 3) * 2;
                const float v0 = c[mi][nj][half * 2];
                const float v1 = c[mi][nj][half * 2 + 1];
                const float2 b2 = *(const float2*)(bias + n);
                if (EPI == 0) {
                    const int part = n >> 10, rr = n & 1023;
                    const int hh = rr >> 6, d = rr & 63;
                    float* dst = (part == 0) ? g_q : ((part == 1) ? g_k : g_v);
                    const int bidx = r >> 11, srow = r & 2047;
                    *(float2*)(dst + ((size_t)((bidx * NHH + hh) * SS + srow)) * HDD + d) =
                        make_float2(v0 + b2.x, v1 + b2.y);
                } else {
                    const float2 r2 = *(const float2*)(resid + (size_t)r * HH + n);
                    *(float2*)(outp + (size_t)r * HH + n) =
                        make_float2(v0 + b2.x + r2.x, v1 + b2.y + r2.y);
                }
            }
        }
    }
}

// ---------------- flash attention + raw score emission ----------------
#define ATTN_SMEM (3 * 64 * 68 * 4)
__global__ __launch_bounds__(256) void attn_kernel(const float* __restrict__ amask,
                                                   float* __restrict__ scores_out) {
    extern __shared__ float sm[];
    float (*Qst)[68] = (float (*)[68])sm;                 // [d][q]
    float (*KPs)[68] = (float (*)[68])(sm + 64 * 68);     // K as [d][kc], then P^T
    float (*Vs )[68] = (float (*)[68])(sm + 2 * 64 * 68); // [kc][d]

    const int qt = 31 - blockIdx.x;
    const int hidx = blockIdx.y;
    const int b  = blockIdx.z;
    const int tid = threadIdx.x;
    const int ty = tid >> 4, tx = tid & 15;
    const int q0 = qt * 64;

    const float* Qg = g_q + (size_t)(b * NHH + hidx) * SS * HDD;
    const float* Kg = g_k + (size_t)(b * NHH + hidx) * SS * HDD;
    const float* Vg = g_v + (size_t)(b * NHH + hidx) * SS * HDD;
    float* sc = scores_out ? scores_out + ((size_t)(b * NHH + hidx) * SS + q0) * SS : nullptr;
    const float* am_base = amask + b * SS;

    {
        const int r = tid >> 2;
        const int dbase = (tid & 3) * 16;
        const float4* src = (const float4*)(Qg + (size_t)(q0 + r) * HDD + dbase);
        #pragma unroll
        for (int i = 0; i < 4; i++) {
            const float4 v = src[i];
            Qst[dbase + 4*i + 0][r] = v.x; Qst[dbase + 4*i + 1][r] = v.y;
            Qst[dbase + 4*i + 2][r] = v.z; Qst[dbase + 4*i + 3][r] = v.w;
        }
    }

    ull acc2[4][2];
    float mrow[4], lrow[4];
    #pragma unroll
    for (int i = 0; i < 4; i++) {
        mrow[i] = -1e30f; lrow[i] = 0.f;
        acc2[i][0] = 0ull; acc2[i][1] = 0ull;
    }

    for (int kt = 0; kt <= qt; kt++) {
        const int k0 = kt * 64;
        __syncthreads();
        {
            const int r = tid >> 2;
            const int dbase = (tid & 3) * 16;
            const float4* ks = (const float4*)(Kg + (size_t)(k0 + r) * HDD + dbase);
            const float4* vs = (const float4*)(Vg + (size_t)(k0 + r) * HDD + dbase);
            #pragma unroll
            for (int i = 0; i < 4; i++) {
                const float4 kv = ks[i];
                KPs[dbase + 4*i + 0][r] = kv.x; KPs[dbase + 4*i + 1][r] = kv.y;
                KPs[dbase + 4*i + 2][r] = kv.z; KPs[dbase + 4*i + 3][r] = kv.w;
                *(float4*)&Vs[r][dbase + 4*i] = vs[i];
            }
        }
        __syncthreads();

        ull s2[4][2];
        #pragma unroll
        for (int i = 0; i < 4; i++) { s2[i][0] = 0ull; s2[i][1] = 0ull; }
        #pragma unroll
        for (int kk = 0; kk < 64; kk++) {
            const float4 qf = *(const float4*)&Qst[kk][ty * 4];
            const ull* kp = (const ull*)&KPs[kk][tx * 4];
            const ull kk0 = kp[0], kk1 = kp[1];
            const float qa[4] = {qf.x, qf.y, qf.z, qf.w};
            #pragma unroll
            for (int i = 0; i < 4; i++) {
                const ull qi = pack2(qa[i]);
                s2[i][0] = ffma2(qi, kk0, s2[i][0]);
                s2[i][1] = ffma2(qi, kk1, s2[i][1]);
            }
        }

        float s[4][4];
        #pragma unroll
        for (int i = 0; i < 4; i++) {
            const float2 v0 = unpack2(s2[i][0]);
            const float2 v1 = unpack2(s2[i][1]);
            s[i][0] = v0.x; s[i][1] = v0.y; s[i][2] = v1.x; s[i][3] = v1.y;
        }

        const float4 am4 = *(const float4*)(am_base + k0 + tx * 4);
        const float am[4] = {am4.x, am4.y, am4.z, am4.w};
        const bool diag = (kt == qt);
        #pragma unroll
        for (int i = 0; i < 4; i++) {
            const int qg = q0 + ty * 4 + i;
            #pragma unroll
            for (int j = 0; j < 4; j++) {
                float v = s[i][j] * 0.125f;
                if (diag && (k0 + tx * 4 + j) > qg) v = -10000.0f;
                v += am[j] * -10000.0f;
                s[i][j] = v;
            }
        }
        if (sc) {
            #pragma unroll
            for (int i = 0; i < 4; i++)
                *(float4*)&sc[(size_t)(ty * 4 + i) * SS + k0 + tx * 4] =
                    make_float4(s[i][0], s[i][1], s[i][2], s[i][3]);
        }

        #pragma unroll
        for (int i = 0; i < 4; i++) {
            float tmax = fmaxf(fmaxf(s[i][0], s[i][1]), fmaxf(s[i][2], s[i][3]));
            #pragma unroll
            for (int o = 8; o > 0; o >>= 1)
                tmax = fmaxf(tmax, __shfl_xor_sync(0xffffffffu, tmax, o, 16));
            const float mnew = fmaxf(mrow[i], tmax);
            const float alpha = __expf(mrow[i] - mnew);
            float psum = 0.f;
            #pragma unroll
            for (int j = 0; j < 4; j++) { s[i][j] = __expf(s[i][j] - mnew); psum += s[i][j]; }
            #pragma unroll
            for (int o = 8; o > 0; o >>= 1)
                psum += __shfl_xor_sync(0xffffffffu, psum, o, 16);
            lrow[i] = lrow[i] * alpha + psum;
            mrow[i] = mnew;
            const ull al2 = pack2(alpha);
            acc2[i][0] = fmul2(acc2[i][0], al2);
            acc2[i][1] = fmul2(acc2[i][1], al2);
        }

        __syncthreads();
        #pragma unroll
        for (int i = 0; i < 4; i++)
            #pragma unroll
            for (int j = 0; j < 4; j++) KPs[tx * 4 + j][ty * 4 + i] = s[i][j];  // P^T
        __syncthreads();

        #pragma unroll
        for (int kk = 0; kk < 64; kk++) {
            const float4 pf = *(const float4*)&KPs[kk][ty * 4];
            const ull* vp = (const ull*)&Vs[kk][tx * 4];
            const ull vv0 = vp[0], vv1 = vp[1];
            const float pa[4] = {pf.x, pf.y, pf.z, pf.w};
            #pragma unroll
            for (int i = 0; i < 4; i++) {
                const ull pi = pack2(pa[i]);
                acc2[i][0] = ffma2(pi, vv0, acc2[i][0]);
                acc2[i][1] = ffma2(pi, vv1, acc2[i][1]);
            }
        }
    }

    if (sc) {
        for (int kt = qt + 1; kt < 32; kt++) {
            const int k0 = kt * 64;
            const float4 am4 = *(const float4*)(am_base + k0 + tx * 4);
            float4 val;
            val.x = -10000.0f + am4.x * -10000.0f;
            val.y = -10000.0f + am4.y * -10000.0f;
            val.z = -10000.0f + am4.z * -10000.0f;
            val.w = -10000.0f + am4.w * -10000.0f;
            #pragma unroll
            for (int i = 0; i < 4; i++)
                *(float4*)&sc[(size_t)(ty * 4 + i) * SS + k0 + tx * 4] = val;
        }
    }

    // ctx -> bf16 hi/lo split for proj GEMM
    #pragma unroll
    for (int i = 0; i < 4; i++) {
        const float inv = 1.0f / lrow[i];
        const float2 v0 = unpack2(acc2[i][0]);
        const float2 v1 = unpack2(acc2[i][1]);
        const float o[4] = {v0.x * inv, v0.y * inv, v1.x * inv, v1.y * inv};
        __nv_bfloat16 h[4], l[4];
        #pragma unroll
        for (int j = 0; j < 4; j++) {
            h[j] = __float2bfloat16(o[j]);
            l[j] = __float2bfloat16(o[j] - __bfloat162float(h[j]));
        }
        const size_t off = ((size_t)(b * SS) + q0 + ty * 4 + i) * HH + hidx * HDD + tx * 4;
        *(__nv_bfloat162*)(g_ch + off)     = __nv_bfloat162(h[0], h[1]);
        *(__nv_bfloat162*)(g_ch + off + 2) = __nv_bfloat162(h[2], h[3]);
        *(__nv_bfloat162*)(g_cl + off)     = __nv_bfloat162(l[0], l[1]);
        *(__nv_bfloat162*)(g_cl + off + 2) = __nv_bfloat162(l[2], l[3]);
    }
}

// ---------------- launch ----------------
extern "C" void kernel_launch(void* const* d_in, const int* in_sizes, int n_in,
                              void* d_out, int out_size) {
    const float* hs       = (const float*)d_in[0];
    const float* amask    = (const float*)d_in[1];
    const float* c_attn_w = (const float*)d_in[2];
    const float* c_attn_b = (const float*)d_in[3];
    const float* c_proj_w = (const float*)d_in[4];
    const float* c_proj_b = (const float*)d_in[5];
    const float* ln_g     = (const float*)d_in[6];
    const float* ln_b     = (const float*)d_in[7];
    float* out = (float*)d_out;
    float* scores = (out_size > MM * HH) ? (out + (size_t)MM * HH) : nullptr;

    __nv_bfloat16 *xh, *xl, *wqh, *wql, *wph, *wpl, *ch, *cl;
    cudaGetSymbolAddress((void**)&xh,  g_xh);
    cudaGetSymbolAddress((void**)&xl,  g_xl);
    cudaGetSymbolAddress((void**)&wqh, g_wqh);
    cudaGetSymbolAddress((void**)&wql, g_wql);
    cudaGetSymbolAddress((void**)&wph, g_wph);
    cudaGetSymbolAddress((void**)&wpl, g_wpl);
    cudaGetSymbolAddress((void**)&ch,  g_ch);
    cudaGetSymbolAddress((void**)&cl,  g_cl);

    cudaFuncSetAttribute(mma_gemm_kernel<0>, cudaFuncAttributeMaxDynamicSharedMemorySize, MMA_SMEM);
    cudaFuncSetAttribute(mma_gemm_kernel<1>, cudaFuncAttributeMaxDynamicSharedMemorySize, MMA_SMEM);
    cudaFuncSetAttribute(attn_kernel, cudaFuncAttributeMaxDynamicSharedMemorySize, ATTN_SMEM);

    ln_kernel<<<MM, 256>>>(hs, ln_g, ln_b);
    wsplit_kernel<<<dim3(N3 / 32, KK / 32), 256>>>(c_attn_w, wqh, wql, N3);
    wsplit_kernel<<<dim3(HH / 32, KK / 32), 256>>>(c_proj_w, wph, wpl, HH);
    mma_gemm_kernel<0><<<dim3(N3 / 128, MM / 128), 256, MMA_SMEM>>>(
        xh, xl, wqh, wql, c_attn_b, nullptr, nullptr);
    attn_kernel<<<dim3(32, NHH, BB), 256, ATTN_SMEM>>>(amask, scores);
    mma_gemm_kernel<1><<<dim3(HH / 128, MM / 128), 256, MMA_SMEM>>>(
        ch, cl, wph, wpl, c_proj_b, hs, out);
}

// round 7
// speedup vs baseline: 1.3284x; 1.3284x over previous
#include <cuda_runtime.h>
#include <cuda_bf16.h>
#include <cstdint>

#define BB   4
#define SS   2048
#define HH   1024
#define NHH  16
#define HDD  64
#define MM   (BB*SS)      // 8192
#define N3   (3*HH)       // 3072
#define KK   1024
#define STR  40           // gemm smem row stride in bf16 (80B -> conflict-free ldmatrix)
#define ASTR 72           // attn Q/K smem stride in bf16 (144B -> conflict-free)
#define VSTR 136          // attn V^T smem stride in bf16 (272B -> conflict-free)

typedef unsigned long long ull;

// ---------------- tensor-core helpers (arch-portable mma.sync path) ----------------
__device__ __forceinline__ uint32_t smem_u32(const void* p) {
    uint32_t a;
    asm("{ .reg .u64 t; cvta.to.shared.u64 t, %1; cvt.u32.u64 %0, t; }" : "=r"(a) : "l"(p));
    return a;
}
__device__ __forceinline__ void ldsm4(uint32_t* r, uint32_t addr) {
    asm volatile("ldmatrix.sync.aligned.m8n8.x4.shared.b16 {%0,%1,%2,%3}, [%4];"
        : "=r"(r[0]), "=r"(r[1]), "=r"(r[2]), "=r"(r[3]) : "r"(addr));
}
__device__ __forceinline__ void mma16816(float* c, const uint32_t* a, const uint32_t* b) {
    asm volatile("mma.sync.aligned.m16n8k16.row.col.f32.bf16.bf16.f32 "
        "{%0,%1,%2,%3}, {%4,%5,%6,%7}, {%8,%9}, {%0,%1,%2,%3};"
        : "+f"(c[0]), "+f"(c[1]), "+f"(c[2]), "+f"(c[3])
        : "r"(a[0]), "r"(a[1]), "r"(a[2]), "r"(a[3]), "r"(b[0]), "r"(b[1]));
}

// fast exp on the FMA pipe (no MUFU): e^x for x <= 0
__device__ __forceinline__ float fexp(float x) {
    float y = x * 1.4426950408889634f;
    y = fmaxf(y, -120.0f);
    const float SH = 12582912.0f;     // 1.5 * 2^23
    float z = y + SH;
    int n = __float_as_int(z) - 0x4B400000;
    float f = y - (z - SH);
    float p = 1.3333558146e-3f;
    p = fmaf(p, f, 9.6181291076e-3f);
    p = fmaf(p, f, 5.5504108665e-2f);
    p = fmaf(p, f, 2.4022650696e-1f);
    p = fmaf(p, f, 6.9314718056e-1f);
    p = fmaf(p, f, 1.0f);
    return __int_as_float(__float_as_int(p) + (n << 23));
}

// split (x,y) into packed bf16x2 hi + lo residual
__device__ __forceinline__ void bsplit2(float x, float y, uint32_t& hi, uint32_t& lo) {
    __nv_bfloat16 hx = __float2bfloat16(x);
    __nv_bfloat16 hy = __float2bfloat16(y);
    __nv_bfloat162 H(hx, hy);
    __nv_bfloat162 L(__float2bfloat16(x - __bfloat162float(hx)),
                     __float2bfloat16(y - __bfloat162float(hy)));
    hi = *reinterpret_cast<uint32_t*>(&H);
    lo = *reinterpret_cast<uint32_t*>(&L);
}

// ---------------- scratch (__device__ globals; no runtime alloc) ----------------
__device__ __align__(128) __nv_bfloat16 g_xh[(size_t)MM * KK];     // LN out hi
__device__ __align__(128) __nv_bfloat16 g_xl[(size_t)MM * KK];     // LN out lo
__device__ __align__(128) __nv_bfloat16 g_wqh[(size_t)N3 * KK];    // qkv W^T hi
__device__ __align__(128) __nv_bfloat16 g_wql[(size_t)N3 * KK];
__device__ __align__(128) __nv_bfloat16 g_wph[(size_t)HH * KK];    // proj W^T hi
__device__ __align__(128) __nv_bfloat16 g_wpl[(size_t)HH * KK];
__device__ __align__(128) __nv_bfloat16 g_ch[(size_t)MM * HH];     // ctx hi
__device__ __align__(128) __nv_bfloat16 g_cl[(size_t)MM * HH];     // ctx lo
__device__ float g_q[(size_t)BB * NHH * SS * HDD];                 // [b,h,s,d]
__device__ float g_k[(size_t)BB * NHH * SS * HDD];
__device__ float g_v[(size_t)BB * NHH * SS * HDD];

// ---------------- layernorm + bf16 hi/lo split ----------------
__global__ __launch_bounds__(256) void ln_kernel(const float* __restrict__ hs,
                                                 const float* __restrict__ gamma,
                                                 const float* __restrict__ beta) {
    const int row = blockIdx.x;
    const int tid = threadIdx.x;
    const float4 v = ((const float4*)(hs + (size_t)row * HH))[tid];
    float s  = v.x + v.y + v.z + v.w;
    float s2 = v.x*v.x + v.y*v.y + v.z*v.z + v.w*v.w;
    #pragma unroll
    for (int o = 16; o > 0; o >>= 1) {
        s  += __shfl_xor_sync(0xffffffffu, s,  o);
        s2 += __shfl_xor_sync(0xffffffffu, s2, o);
    }
    __shared__ float red[2][8];
    const int wid = tid >> 5, lane = tid & 31;
    if (lane == 0) { red[0][wid] = s; red[1][wid] = s2; }
    __syncthreads();
    float mean = 0.f, msq = 0.f;
    #pragma unroll
    for (int i = 0; i < 8; i++) { mean += red[0][i]; msq += red[1][i]; }
    mean *= (1.0f / HH);
    msq  *= (1.0f / HH);
    const float rstd = rsqrtf(msq - mean * mean + 1e-5f);
    const float4 g = ((const float4*)gamma)[tid];
    const float4 b = ((const float4*)beta)[tid];
    float o[4];
    o[0] = (v.x - mean) * rstd * g.x + b.x;
    o[1] = (v.y - mean) * rstd * g.y + b.y;
    o[2] = (v.z - mean) * rstd * g.z + b.z;
    o[3] = (v.w - mean) * rstd * g.w + b.w;
    const size_t off = (size_t)row * HH + tid * 4;
    uint32_t h0, l0, h1, l1;
    bsplit2(o[0], o[1], h0, l0);
    bsplit2(o[2], o[3], h1, l1);
    *(uint32_t*)(g_xh + off)     = h0;
    *(uint32_t*)(g_xh + off + 2) = h1;
    *(uint32_t*)(g_xl + off)     = l0;
    *(uint32_t*)(g_xl + off + 2) = l1;
}

// ---------------- weight transpose + split: W[K=1024, N] -> WT_h/WT_l [N, 1024] ----
__global__ __launch_bounds__(256) void wsplit_kernel(const float* __restrict__ W,
                                                     __nv_bfloat16* __restrict__ Th,
                                                     __nv_bfloat16* __restrict__ Tl,
                                                     int N) {
    __shared__ float sm[32][33];
    const int n0 = blockIdx.x * 32, k0 = blockIdx.y * 32;
    const int tx = threadIdx.x & 31, ty = threadIdx.x >> 5;
    #pragma unroll
    for (int i = 0; i < 4; i++) {
        const int k = ty * 4 + i;
        sm[k][tx] = W[(size_t)(k0 + k) * N + n0 + tx];
    }
    __syncthreads();
    #pragma unroll
    for (int i = 0; i < 4; i++) {
        const int n = ty * 4 + i;
        const float v = sm[tx][n];
        const __nv_bfloat16 h = __float2bfloat16(v);
        const __nv_bfloat16 l = __float2bfloat16(v - __bfloat162float(h));
        Th[(size_t)(n0 + n) * KK + k0 + tx] = h;
        Tl[(size_t)(n0 + n) * KK + k0 + tx] = l;
    }
}

// ---------------- split-bf16 mma.sync GEMM: C[128x128] = A[M,K] @ B[N,K]^T ----------
#define MMA_SMEM (8 * 128 * STR * 2)
template<int EPI>
__global__ __launch_bounds__(256) void mma_gemm_kernel(
    const __nv_bfloat16* __restrict__ Ah, const __nv_bfloat16* __restrict__ Al,
    const __nv_bfloat16* __restrict__ Bh, const __nv_bfloat16* __restrict__ Bl,
    const float* __restrict__ bias, const float* __restrict__ resid,
    float* __restrict__ outp)
{
    extern __shared__ __nv_bfloat16 smb[];
    const int tid = threadIdx.x, wid = tid >> 5, lane = tid & 31;
    const int bm = blockIdx.y, bn = blockIdx.x;
    const int wm = wid >> 2, wn = wid & 3;
    const uint32_t sbase = smem_u32(smb);

    const __nv_bfloat16* gA0 = Ah + (size_t)bm * 128 * KK;
    const __nv_bfloat16* gA1 = Al + (size_t)bm * 128 * KK;
    const __nv_bfloat16* gB0 = Bh + (size_t)bn * 128 * KK;
    const __nv_bfloat16* gB1 = Bl + (size_t)bn * 128 * KK;

    float c[4][4][4];
    #pragma unroll
    for (int i = 0; i < 4; i++)
        #pragma unroll
        for (int j = 0; j < 4; j++)
            #pragma unroll
            for (int q = 0; q < 4; q++) c[i][j][q] = 0.f;

    const int lrow = tid >> 2;
    const int lseg = tid & 3;

    uint4 pre[4][2];
    auto gload = [&](int k0) {
        #pragma unroll
        for (int op = 0; op < 4; op++) {
            const __nv_bfloat16* src = (op == 0) ? gA0 : (op == 1) ? gA1 : (op == 2) ? gB0 : gB1;
            #pragma unroll
            for (int i = 0; i < 2; i++) {
                const int row = lrow + i * 64;
                pre[op][i] = *(const uint4*)(src + (size_t)row * KK + k0 + lseg * 8);
            }
        }
    };
    auto s2s = [&](int buf) {
        #pragma unroll
        for (int op = 0; op < 4; op++)
            #pragma unroll
            for (int i = 0; i < 2; i++) {
                const int row = lrow + i * 64;
                *(uint4*)(smb + (size_t)(buf * 4 + op) * 128 * STR + row * STR + lseg * 8) = pre[op][i];
            }
    };

    gload(0);
    s2s(0);
    __syncthreads();

    const int a_r = lane & 15;
    const int a_c = (lane >> 4) * 8;
    const int b_r = ((lane >> 4) << 3) + (lane & 7);
    const int b_c = ((lane >> 3) & 1) * 8;

    const int NCH = KK / 32;
    for (int ch = 0; ch < NCH; ch++) {
        const int buf = ch & 1;
        if (ch + 1 < NCH) gload((ch + 1) * 32);
        #pragma unroll
        for (int pass = 0; pass < 3; pass++) {
            const int aop = (pass == 2) ? 1 : 0;
            const int bop = (pass == 1) ? 3 : 2;
            const uint32_t abase = sbase + (uint32_t)((buf * 4 + aop) * 128 * STR) * 2;
            const uint32_t bbase = sbase + (uint32_t)((buf * 4 + bop) * 128 * STR) * 2;
            #pragma unroll
            for (int ks = 0; ks < 2; ks++) {
                uint32_t a[4][4], b[2][4];
                #pragma unroll
                for (int mi = 0; mi < 4; mi++)
                    ldsm4(a[mi], abase + (uint32_t)((wm * 64 + mi * 16 + a_r) * STR + ks * 16 + a_c) * 2);
                #pragma unroll
                for (int pj = 0; pj < 2; pj++)
                    ldsm4(b[pj], bbase + (uint32_t)((wn * 32 + pj * 16 + b_r) * STR + ks * 16 + b_c) * 2);
                #pragma unroll
                for (int mi = 0; mi < 4; mi++)
                    #pragma unroll
                    for (int nj = 0; nj < 4; nj++)
                        mma16816(c[mi][nj], a[mi], &b[nj >> 1][(nj & 1) * 2]);
            }
        }
        if (ch + 1 < NCH) s2s(1 - buf);
        __syncthreads();
    }

    #pragma unroll
    for (int mi = 0; mi < 4; mi++) {
        #pragma unroll
        for (int half = 0; half < 2; half++) {
            const int r = bm * 128 + wm * 64 + mi * 16 + (lane >> 2) + half * 8;
            #pragma unroll
            for (int nj = 0; nj < 4; nj++) {
                const int n = bn * 128 + wn * 32 + nj * 8 + (lane & 3) * 2;
                const float v0 = c[mi][nj][half * 2];
                const float v1 = c[mi][nj][half * 2 + 1];
                const float2 b2 = *(const float2*)(bias + n);
                if (EPI == 0) {
                    const int part = n >> 10, rr = n & 1023;
                    const int hh = rr >> 6, d = rr & 63;
                    float* dst = (part == 0) ? g_q : ((part == 1) ? g_k : g_v);
                    const int bidx = r >> 11, srow = r & 2047;
                    *(float2*)(dst + ((size_t)((bidx * NHH + hh) * SS + srow)) * HDD + d) =
                        make_float2(v0 + b2.x, v1 + b2.y);
                } else {
                    const float2 r2 = *(const float2*)(resid + (size_t)r * HH + n);
                    *(float2*)(outp + (size_t)r * HH + n) =
                        make_float2(v0 + b2.x + r2.x, v1 + b2.y + r2.y);
                }
            }
        }
    }
}

// ---------------- tensor-core flash attention + raw score emission ----------------
// block = (b, h, 128-q-row tile). 256 threads = 8 warps; warp w owns rows w*16..w*16+15.
#define ATTN2_SMEM ((4 * 128 * ASTR + 2 * 64 * VSTR) * 2)
__global__ __launch_bounds__(256) void attn_mma_kernel(const float* __restrict__ amask,
                                                       float* __restrict__ scores_out) {
    extern __shared__ __nv_bfloat16 smb[];
    __nv_bfloat16* Qh  = smb;                  // [128][ASTR]
    __nv_bfloat16* Ql  = Qh  + 128 * ASTR;
    __nv_bfloat16* Kh  = Ql  + 128 * ASTR;
    __nv_bfloat16* Kl  = Kh  + 128 * ASTR;
    __nv_bfloat16* Vth = Kl  + 128 * ASTR;     // [64][VSTR] (d-major, key contiguous)
    __nv_bfloat16* Vtl = Vth + 64 * VSTR;

    const int qt = 15 - blockIdx.x;            // heavy tiles first
    const int hq = blockIdx.y;
    const int bb = blockIdx.z;
    const int tid = threadIdx.x, w = tid >> 5, lane = tid & 31;
    const int q0 = qt * 128;

    const float* Qg = g_q + (size_t)(bb * NHH + hq) * SS * HDD;
    const float* Kg = g_k + (size_t)(bb * NHH + hq) * SS * HDD;
    const float* Vg = g_v + (size_t)(bb * NHH + hq) * SS * HDD;
    float* sc = scores_out + ((size_t)(bb * NHH + hq) * SS + q0) * SS;
    const float* amk = amask + bb * SS;

    // ---- load Q tile (128x64), split hi/lo ----
    #pragma unroll
    for (int i = 0; i < 8; i++) {
        const int idx4 = tid + i * 256;
        const int r = idx4 >> 4, cg = (idx4 & 15) * 4;
        const float4 v = *(const float4*)(Qg + (size_t)(q0 + r) * HDD + cg);
        uint32_t h0, l0, h1, l1;
        bsplit2(v.x, v.y, h0, l0);
        bsplit2(v.z, v.w, h1, l1);
        *(uint32_t*)(Qh + r * ASTR + cg)     = h0;
        *(uint32_t*)(Qh + r * ASTR + cg + 2) = h1;
        *(uint32_t*)(Ql + r * ASTR + cg)     = l0;
        *(uint32_t*)(Ql + r * ASTR + cg + 2) = l1;
    }

    float ctx[8][4];
    #pragma unroll
    for (int j = 0; j < 8; j++)
        #pragma unroll
        for (int q = 0; q < 4; q++) ctx[j][q] = 0.f;
    float mrow1 = -1e30f, mrow2 = -1e30f, lsum1 = 0.f, lsum2 = 0.f;

    const int a_r = lane & 15, a_c = (lane >> 4) * 8;
    const int b_r = ((lane >> 4) << 3) + (lane & 7), b_c = ((lane >> 3) & 1) * 8;
    const int colb = (lane & 3) * 2;
    const int rt1 = w * 16 + (lane >> 2), rt2 = rt1 + 8;
    const int qg1 = q0 + rt1, qg2 = q0 + rt2;

    const uint32_t qhb = smem_u32(Qh), qlb = smem_u32(Ql);
    const uint32_t khb = smem_u32(Kh), klb = smem_u32(Kl);
    const uint32_t vhb = smem_u32(Vth), vlb = smem_u32(Vtl);

    for (int kt = 0; kt <= qt; kt++) {
        const int k0 = kt * 128;
        __syncthreads();   // prior-iteration smem readers done (also orders Q store on kt=0)
        // ---- load K tile (coalesced) ----
        #pragma unroll
        for (int i = 0; i < 8; i++) {
            const int idx4 = tid + i * 256;
            const int r = idx4 >> 4, cg = (idx4 & 15) * 4;
            const float4 v = *(const float4*)(Kg + (size_t)(k0 + r) * HDD + cg);
            uint32_t h0, l0, h1, l1;
            bsplit2(v.x, v.y, h0, l0);
            bsplit2(v.z, v.w, h1, l1);
            *(uint32_t*)(Kh + r * ASTR + cg)     = h0;
            *(uint32_t*)(Kh + r * ASTR + cg + 2) = h1;
            *(uint32_t*)(Kl + r * ASTR + cg)     = l0;
            *(uint32_t*)(Kl + r * ASTR + cg + 2) = l1;
        }
        // ---- load V tile transposed: Vt[d][key] ----
        #pragma unroll
        for (int t = 0; t < 4; t++) {
            const int task = tid + t * 256;
            const int kp = task & 63, dg = (task >> 6) * 4;
            const float4 v0 = *(const float4*)(Vg + (size_t)(k0 + 2 * kp) * HDD + dg);
            const float4 v1 = *(const float4*)(Vg + (size_t)(k0 + 2 * kp + 1) * HDD + dg);
            const float* p0 = &v0.x;
            const float* p1 = &v1.x;
            #pragma unroll
            for (int dd = 0; dd < 4; dd++) {
                uint32_t hi, lo;
                bsplit2(p0[dd], p1[dd], hi, lo);
                *(uint32_t*)(Vth + (dg + dd) * VSTR + 2 * kp) = hi;
                *(uint32_t*)(Vtl + (dg + dd) * VSTR + 2 * kp) = lo;
            }
        }
        __syncthreads();

        // ---- S = Q K^T (3-pass split bf16) ----
        float S[16][4];
        #pragma unroll
        for (int j = 0; j < 16; j++)
            #pragma unroll
            for (int q = 0; q < 4; q++) S[j][q] = 0.f;
        #pragma unroll
        for (int pass = 0; pass < 3; pass++) {
            const uint32_t abase = (pass == 2) ? qlb : qhb;
            const uint32_t bbase = (pass == 1) ? klb : khb;
            #pragma unroll
            for (int kg = 0; kg < 4; kg++) {
                uint32_t a[4];
                ldsm4(a, abase + (uint32_t)((w * 16 + a_r) * ASTR + kg * 16 + a_c) * 2);
                #pragma unroll
                for (int pj = 0; pj < 8; pj++) {
                    uint32_t bf[4];
                    ldsm4(bf, bbase + (uint32_t)((pj * 16 + b_r) * ASTR + kg * 16 + b_c) * 2);
                    mma16816(S[2 * pj],     a, &bf[0]);
                    mma16816(S[2 * pj + 1], a, &bf[2]);
                }
            }
        }

        // ---- scale, causal, amask, emit raw scores ----
        const bool diag = (kt == qt);
        #pragma unroll
        for (int j = 0; j < 16; j++) {
            const int c0 = k0 + j * 8 + colb;
            const float2 am2 = *(const float2*)(amk + c0);
            const float mk0 = am2.x * -10000.f, mk1 = am2.y * -10000.f;
            float s0 = fmaf(S[j][0], 0.125f, mk0);
            float s1 = fmaf(S[j][1], 0.125f, mk1);
            float s2 = fmaf(S[j][2], 0.125f, mk0);
            float s3 = fmaf(S[j][3], 0.125f, mk1);
            if (diag) {
                if (c0     > qg1) s0 = -10000.f + mk0;
                if (c0 + 1 > qg1) s1 = -10000.f + mk1;
                if (c0     > qg2) s2 = -10000.f + mk0;
                if (c0 + 1 > qg2) s3 = -10000.f + mk1;
            }
            *(float2*)(sc + (size_t)rt1 * SS + c0) = make_float2(s0, s1);
            *(float2*)(sc + (size_t)rt2 * SS + c0) = make_float2(s2, s3);
            S[j][0] = s0; S[j][1] = s1; S[j][2] = s2; S[j][3] = s3;
        }

        // ---- online softmax (FMA-pipe exp) ----
        float mx1 = -1e30f, mx2 = -1e30f;
        #pragma unroll
        for (int j = 0; j < 16; j++) {
            mx1 = fmaxf(mx1, fmaxf(S[j][0], S[j][1]));
            mx2 = fmaxf(mx2, fmaxf(S[j][2], S[j][3]));
        }
        mx1 = fmaxf(mx1, __shfl_xor_sync(0xffffffffu, mx1, 1));
        mx1 = fmaxf(mx1, __shfl_xor_sync(0xffffffffu, mx1, 2));
        mx2 = fmaxf(mx2, __shfl_xor_sync(0xffffffffu, mx2, 1));
        mx2 = fmaxf(mx2, __shfl_xor_sync(0xffffffffu, mx2, 2));
        const float mn1 = fmaxf(mrow1, mx1), mn2 = fmaxf(mrow2, mx2);
        const float al1 = fexp(mrow1 - mn1), al2 = fexp(mrow2 - mn2);
        float sum1 = 0.f, sum2 = 0.f;
        #pragma unroll
        for (int j = 0; j < 16; j++) {
            S[j][0] = fexp(S[j][0] - mn1);
            S[j][1] = fexp(S[j][1] - mn1);
            S[j][2] = fexp(S[j][2] - mn2);
            S[j][3] = fexp(S[j][3] - mn2);
            sum1 += S[j][0] + S[j][1];
            sum2 += S[j][2] + S[j][3];
        }
        sum1 += __shfl_xor_sync(0xffffffffu, sum1, 1);
        sum1 += __shfl_xor_sync(0xffffffffu, sum1, 2);
        sum2 += __shfl_xor_sync(0xffffffffu, sum2, 1);
        sum2 += __shfl_xor_sync(0xffffffffu, sum2, 2);
        lsum1 = lsum1 * al1 + sum1; mrow1 = mn1;
        lsum2 = lsum2 * al2 + sum2; mrow2 = mn2;
        #pragma unroll
        for (int j = 0; j < 8; j++) {
            ctx[j][0] *= al1; ctx[j][1] *= al1;
            ctx[j][2] *= al2; ctx[j][3] *= al2;
        }

        // ---- ctx += P V (P from registers, 3-pass split) ----
        #pragma unroll
        for (int kg = 0; kg < 8; kg++) {
            uint32_t ah[4], alr[4];
            bsplit2(S[2 * kg][0],     S[2 * kg][1],     ah[0], alr[0]);
            bsplit2(S[2 * kg][2],     S[2 * kg][3],     ah[1], alr[1]);
            bsplit2(S[2 * kg + 1][0], S[2 * kg + 1][1], ah[2], alr[2]);
            bsplit2(S[2 * kg + 1][2], S[2 * kg + 1][3], ah[3], alr[3]);
            #pragma unroll
            for (int pj = 0; pj < 4; pj++) {
                const uint32_t off = (uint32_t)((pj * 16 + b_r) * VSTR + kg * 16 + b_c) * 2;
                uint32_t bh4[4], bl4[4];
                ldsm4(bh4, vhb + off);
                ldsm4(bl4, vlb + off);
                mma16816(ctx[2 * pj],     ah,  &bh4[0]);
                mma16816(ctx[2 * pj],     alr, &bh4[0]);
                mma16816(ctx[2 * pj],     ah,  &bl4[0]);
                mma16816(ctx[2 * pj + 1], ah,  &bh4[2]);
                mma16816(ctx[2 * pj + 1], alr, &bh4[2]);
                mma16816(ctx[2 * pj + 1], ah,  &bl4[2]);
            }
        }
    }

    // ---- tail tiles: fully causal-masked scores fill ----
    {
        const int r = tid >> 1, ch0 = (tid & 1) * 64;
        for (int kt2 = qt + 1; kt2 < 16; kt2++) {
            const int k0 = kt2 * 128;
            #pragma unroll
            for (int i = 0; i < 16; i++) {
                const int c = ch0 + i * 4;
                const float4 a4 = *(const float4*)(amk + k0 + c);
                const float4 val = make_float4(-10000.f + a4.x * -10000.f,
                                               -10000.f + a4.y * -10000.f,
                                               -10000.f + a4.z * -10000.f,
                                               -10000.f + a4.w * -10000.f);
                *(float4*)(sc + (size_t)r * SS + k0 + c) = val;
            }
        }
    }

    // ---- ctx /= lsum -> bf16 hi/lo for proj ----
    const float inv1 = 1.0f / lsum1, inv2 = 1.0f / lsum2;
    #pragma unroll
    for (int j = 0; j < 8; j++) {
        const int d = hq * 64 + j * 8 + colb;
        const size_t o1 = ((size_t)(bb * SS) + q0 + rt1) * HH + d;
        const size_t o2 = ((size_t)(bb * SS) + q0 + rt2) * HH + d;
        uint32_t hi, lo;
        bsplit2(ctx[j][0] * inv1, ctx[j][1] * inv1, hi, lo);
        *(uint32_t*)(g_ch + o1) = hi;
        *(uint32_t*)(g_cl + o1) = lo;
        bsplit2(ctx[j][2] * inv2, ctx[j][3] * inv2, hi, lo);
        *(uint32_t*)(g_ch + o2) = hi;
        *(uint32_t*)(g_cl + o2) = lo;
    }
}

// ---------------- launch ----------------
extern "C" void kernel_launch(void* const* d_in, const int* in_sizes, int n_in,
                              void* d_out, int out_size) {
    const float* hs       = (const float*)d_in[0];
    const float* amask    = (const float*)d_in[1];
    const float* c_attn_w = (const float*)d_in[2];
    const float* c_attn_b = (const float*)d_in[3];
    const float* c_proj_w = (const float*)d_in[4];
    const float* c_proj_b = (const float*)d_in[5];
    const float* ln_g     = (const float*)d_in[6];
    const float* ln_b     = (const float*)d_in[7];
    float* out = (float*)d_out;
    float* scores = out + (size_t)MM * HH;

    __nv_bfloat16 *xh, *xl, *wqh, *wql, *wph, *wpl, *ch, *cl;
    cudaGetSymbolAddress((void**)&xh,  g_xh);
    cudaGetSymbolAddress((void**)&xl,  g_xl);
    cudaGetSymbolAddress((void**)&wqh, g_wqh);
    cudaGetSymbolAddress((void**)&wql, g_wql);
    cudaGetSymbolAddress((void**)&wph, g_wph);
    cudaGetSymbolAddress((void**)&wpl, g_wpl);
    cudaGetSymbolAddress((void**)&ch,  g_ch);
    cudaGetSymbolAddress((void**)&cl,  g_cl);

    cudaFuncSetAttribute(mma_gemm_kernel<0>, cudaFuncAttributeMaxDynamicSharedMemorySize, MMA_SMEM);
    cudaFuncSetAttribute(mma_gemm_kernel<1>, cudaFuncAttributeMaxDynamicSharedMemorySize, MMA_SMEM);
    cudaFuncSetAttribute(attn_mma_kernel, cudaFuncAttributeMaxDynamicSharedMemorySize, ATTN2_SMEM);

    ln_kernel<<<MM, 256>>>(hs, ln_g, ln_b);
    wsplit_kernel<<<dim3(N3 / 32, KK / 32), 256>>>(c_attn_w, wqh, wql, N3);
    wsplit_kernel<<<dim3(HH / 32, KK / 32), 256>>>(c_proj_w, wph, wpl, HH);
    mma_gemm_kernel<0><<<dim3(N3 / 128, MM / 128), 256, MMA_SMEM>>>(
        xh, xl, wqh, wql, c_attn_b, nullptr, nullptr);
    attn_mma_kernel<<<dim3(16, NHH, BB), 256, ATTN2_SMEM>>>(amask, scores);
    mma_gemm_kernel<1><<<dim3(HH / 128, MM / 128), 256, MMA_SMEM>>>(
        ch, cl, wph, wpl, c_proj_b, hs, out);
}

// round 12
// speedup vs baseline: 1.5525x; 1.1686x over previous
#include <cuda_runtime.h>
#include <cuda_bf16.h>
#include <cstdint>

#define BB   4
#define SS   2048
#define HH   1024
#define NHH  16
#define HDD  64
#define MM   (BB*SS)      // 8192
#define N3   (3*HH)       // 3072
#define KK   1024
#define STR  40           // gemm smem row stride in bf16 (80B, 16B-aligned, conflict-free)
#define ASTR 72           // attn Q/K smem stride in bf16 (144B)
#define VSTR 136          // attn V^T smem stride in bf16 (272B)

// ---------------- helpers ----------------
__device__ __forceinline__ uint32_t smem_u32(const void* p) {
    uint32_t a;
    asm("{ .reg .u64 t; cvta.to.shared.u64 t, %1; cvt.u32.u64 %0, t; }" : "=r"(a) : "l"(p));
    return a;
}
__device__ __forceinline__ void ldsm4(uint32_t* r, uint32_t addr) {
    asm volatile("ldmatrix.sync.aligned.m8n8.x4.shared.b16 {%0,%1,%2,%3}, [%4];"
        : "=r"(r[0]), "=r"(r[1]), "=r"(r[2]), "=r"(r[3]) : "r"(addr));
}
__device__ __forceinline__ void mma16816(float* c, const uint32_t* a, const uint32_t* b) {
    asm volatile("mma.sync.aligned.m16n8k16.row.col.f32.bf16.bf16.f32 "
        "{%0,%1,%2,%3}, {%4,%5,%6,%7}, {%8,%9}, {%0,%1,%2,%3};"
        : "+f"(c[0]), "+f"(c[1]), "+f"(c[2]), "+f"(c[3])
        : "r"(a[0]), "r"(a[1]), "r"(a[2]), "r"(a[3]), "r"(b[0]), "r"(b[1]));
}
#define CPA(dst, src) asm volatile("cp.async.cg.shared.global [%0], [%1], 16;" :: "r"(dst), "l"(src))
#define CPC() asm volatile("cp.async.commit_group;" ::: "memory")
#define CPW0() asm volatile("cp.async.wait_group 0;" ::: "memory")

// fast exp on the FMA pipe (no MUFU)
__device__ __forceinline__ float fexp(float x) {
    float y = x * 1.4426950408889634f;
    y = fmaxf(y, -120.0f);
    const float SH = 12582912.0f;
    float z = y + SH;
    int n = __float_as_int(z) - 0x4B400000;
    float f = y - (z - SH);
    float p = 1.3333558146e-3f;
    p = fmaf(p, f, 9.6181291076e-3f);
    p = fmaf(p, f, 5.5504108665e-2f);
    p = fmaf(p, f, 2.4022650696e-1f);
    p = fmaf(p, f, 6.9314718056e-1f);
    p = fmaf(p, f, 1.0f);
    return __int_as_float(__float_as_int(p) + (n << 23));
}
__device__ __forceinline__ void bsplit2(float x, float y, uint32_t& hi, uint32_t& lo) {
    __nv_bfloat16 hx = __float2bfloat16(x);
    __nv_bfloat16 hy = __float2bfloat16(y);
    __nv_bfloat162 H(hx, hy);
    __nv_bfloat162 L(__float2bfloat16(x - __bfloat162float(hx)),
                     __float2bfloat16(y - __bfloat162float(hy)));
    hi = *reinterpret_cast<uint32_t*>(&H);
    lo = *reinterpret_cast<uint32_t*>(&L);
}

// ---------------- scratch ----------------
__device__ __align__(128) __nv_bfloat16 g_xh[(size_t)MM * KK];
__device__ __align__(128) __nv_bfloat16 g_xl[(size_t)MM * KK];
__device__ __align__(128) __nv_bfloat16 g_wqh[(size_t)N3 * KK];
__device__ __align__(128) __nv_bfloat16 g_wql[(size_t)N3 * KK];
__device__ __align__(128) __nv_bfloat16 g_wph[(size_t)HH * KK];
__device__ __align__(128) __nv_bfloat16 g_wpl[(size_t)HH * KK];
__device__ __align__(128) __nv_bfloat16 g_ch[(size_t)MM * HH];
__device__ __align__(128) __nv_bfloat16 g_cl[(size_t)MM * HH];
__device__ __align__(128) __nv_bfloat16 g_qh[(size_t)BB * NHH * SS * HDD];  // [b,h,s,d]
__device__ __align__(128) __nv_bfloat16 g_ql[(size_t)BB * NHH * SS * HDD];
__device__ __align__(128) __nv_bfloat16 g_kh[(size_t)BB * NHH * SS * HDD];
__device__ __align__(128) __nv_bfloat16 g_kl[(size_t)BB * NHH * SS * HDD];
__device__ __align__(128) __nv_bfloat16 g_vth[(size_t)BB * NHH * HDD * SS]; // [b,h,d,s]
__device__ __align__(128) __nv_bfloat16 g_vtl[(size_t)BB * NHH * HDD * SS];
__device__ float g_v[(size_t)BB * NHH * SS * HDD];                          // [b,h,s,d] fp32

// ---------------- layernorm + split ----------------
__global__ __launch_bounds__(256) void ln_kernel(const float* __restrict__ hs,
                                                 const float* __restrict__ gamma,
                                                 const float* __restrict__ beta) {
    const int row = blockIdx.x;
    const int tid = threadIdx.x;
    const float4 v = ((const float4*)(hs + (size_t)row * HH))[tid];
    float s  = v.x + v.y + v.z + v.w;
    float s2 = v.x*v.x + v.y*v.y + v.z*v.z + v.w*v.w;
    #pragma unroll
    for (int o = 16; o > 0; o >>= 1) {
        s  += __shfl_xor_sync(0xffffffffu, s,  o);
        s2 += __shfl_xor_sync(0xffffffffu, s2, o);
    }
    __shared__ float red[2][8];
    const int wid = tid >> 5, lane = tid & 31;
    if (lane == 0) { red[0][wid] = s; red[1][wid] = s2; }
    __syncthreads();
    float mean = 0.f, msq = 0.f;
    #pragma unroll
    for (int i = 0; i < 8; i++) { mean += red[0][i]; msq += red[1][i]; }
    mean *= (1.0f / HH);
    msq  *= (1.0f / HH);
    const float rstd = rsqrtf(msq - mean * mean + 1e-5f);
    const float4 g = ((const float4*)gamma)[tid];
    const float4 b = ((const float4*)beta)[tid];
    float o[4];
    o[0] = (v.x - mean) * rstd * g.x + b.x;
    o[1] = (v.y - mean) * rstd * g.y + b.y;
    o[2] = (v.z - mean) * rstd * g.z + b.z;
    o[3] = (v.w - mean) * rstd * g.w + b.w;
    const size_t off = (size_t)row * HH + tid * 4;
    uint32_t h0, l0, h1, l1;
    bsplit2(o[0], o[1], h0, l0);
    bsplit2(o[2], o[3], h1, l1);
    *(uint32_t*)(g_xh + off)     = h0;
    *(uint32_t*)(g_xh + off + 2) = h1;
    *(uint32_t*)(g_xl + off)     = l0;
    *(uint32_t*)(g_xl + off + 2) = l1;
}

// ---------------- weight transpose + split ----------------
__global__ __launch_bounds__(256) void wsplit_kernel(const float* __restrict__ W,
                                                     __nv_bfloat16* __restrict__ Th,
                                                     __nv_bfloat16* __restrict__ Tl,
                                                     int N) {
    __shared__ float sm[32][33];
    const int n0 = blockIdx.x * 32, k0 = blockIdx.y * 32;
    const int tx = threadIdx.x & 31, ty = threadIdx.x >> 5;
    #pragma unroll
    for (int i = 0; i < 4; i++) {
        const int k = ty * 4 + i;
        sm[k][tx] = W[(size_t)(k0 + k) * N + n0 + tx];
    }
    __syncthreads();
    #pragma unroll
    for (int i = 0; i < 4; i++) {
        const int n = ty * 4 + i;
        const float v = sm[tx][n];
        const __nv_bfloat16 h = __float2bfloat16(v);
        const __nv_bfloat16 l = __float2bfloat16(v - __bfloat162float(h));
        Th[(size_t)(n0 + n) * KK + k0 + tx] = h;
        Tl[(size_t)(n0 + n) * KK + k0 + tx] = l;
    }
}

// ---------------- V transpose + split: g_v[bh][s][d] -> g_vth/g_vtl [bh][d][s] ----
__global__ __launch_bounds__(256) void vtrans_kernel() {
    __shared__ float sm[32][33];
    const int s0 = blockIdx.x * 32, d0 = blockIdx.y * 32;
    const int bh = blockIdx.z;
    const int tx = threadIdx.x & 31, ty = threadIdx.x >> 5;
    const float* src = g_v + ((size_t)bh * SS) * HDD;
    #pragma unroll
    for (int i = 0; i < 4; i++) {
        const int k = ty * 4 + i;
        sm[k][tx] = src[(size_t)(s0 + k) * HDD + d0 + tx];
    }
    __syncthreads();
    #pragma unroll
    for (int i = 0; i < 4; i++) {
        const int n = ty * 4 + i;           // d within tile
        const float v = sm[tx][n];          // s = tx
        const __nv_bfloat16 h = __float2bfloat16(v);
        const __nv_bfloat16 l = __float2bfloat16(v - __bfloat162float(h));
        const size_t off = ((size_t)bh * HDD + d0 + n) * SS + s0 + tx;
        g_vth[off] = h;
        g_vtl[off] = l;
    }
}

// ---------------- split-bf16 mma.sync GEMM, cp.async pipelined ----------------
#define MMA_SMEM (8 * 128 * STR * 2)
template<int EPI>
__global__ __launch_bounds__(256) void mma_gemm_kernel(
    const __nv_bfloat16* __restrict__ Ah, const __nv_bfloat16* __restrict__ Al,
    const __nv_bfloat16* __restrict__ Bh, const __nv_bfloat16* __restrict__ Bl,
    const float* __restrict__ bias, const float* __restrict__ resid,
    float* __restrict__ outp)
{
    extern __shared__ __nv_bfloat16 smb[];
    const int tid = threadIdx.x, wid = tid >> 5, lane = tid & 31;
    const int bm = blockIdx.y, bn = blockIdx.x;
    const int wm = wid >> 2, wn = wid & 3;
    const uint32_t sbase = smem_u32(smb);

    const __nv_bfloat16* srcs[4] = {Ah + (size_t)bm * 128 * KK, Al + (size_t)bm * 128 * KK,
                                    Bh + (size_t)bn * 128 * KK, Bl + (size_t)bn * 128 * KK};

    float c[4][4][4];
    #pragma unroll
    for (int i = 0; i < 4; i++)
        #pragma unroll
        for (int j = 0; j < 4; j++)
            #pragma unroll
            for (int q = 0; q < 4; q++) c[i][j][q] = 0.f;

    auto cpload = [&](int buf, int k0) {
        #pragma unroll
        for (int op = 0; op < 4; op++) {
            const __nv_bfloat16* s = srcs[op] + k0;
            const uint32_t dbase = sbase + (uint32_t)((buf * 4 + op) * 128 * STR) * 2;
            #pragma unroll
            for (int i = 0; i < 2; i++) {
                const int id = tid + i * 256;
                const int row = id >> 2, c16 = id & 3;
                CPA(dbase + (uint32_t)(row * STR + c16 * 8) * 2,
                    s + (size_t)row * KK + c16 * 8);
            }
        }
    };
    cpload(0, 0); CPC();

    const int a_r = lane & 15, a_c = (lane >> 4) * 8;
    const int b_r = ((lane >> 4) << 3) + (lane & 7), b_c = ((lane >> 3) & 1) * 8;

    const int NCH = KK / 32;
    for (int ch = 0; ch < NCH; ch++) {
        CPW0();
        __syncthreads();
        if (ch + 1 < NCH) { cpload((ch + 1) & 1, (ch + 1) * 32); CPC(); }
        const int buf = ch & 1;
        const uint32_t base_ah = sbase + (uint32_t)((buf * 4 + 0) * 128 * STR) * 2;
        const uint32_t base_al = sbase + (uint32_t)((buf * 4 + 1) * 128 * STR) * 2;
        const uint32_t base_bh = sbase + (uint32_t)((buf * 4 + 2) * 128 * STR) * 2;
        const uint32_t base_bl = sbase + (uint32_t)((buf * 4 + 3) * 128 * STR) * 2;
        #pragma unroll
        for (int ks = 0; ks < 2; ks++) {
            uint32_t ah[4][4], al[4][4], bh2[2][4], bl2[2][4];
            #pragma unroll
            for (int mi = 0; mi < 4; mi++)
                ldsm4(ah[mi], base_ah + (uint32_t)((wm * 64 + mi * 16 + a_r) * STR + ks * 16 + a_c) * 2);
            #pragma unroll
            for (int pj = 0; pj < 2; pj++)
                ldsm4(bh2[pj], base_bh + (uint32_t)((wn * 32 + pj * 16 + b_r) * STR + ks * 16 + b_c) * 2);
            #pragma unroll
            for (int pj = 0; pj < 2; pj++)
                ldsm4(bl2[pj], base_bl + (uint32_t)((wn * 32 + pj * 16 + b_r) * STR + ks * 16 + b_c) * 2);
            #pragma unroll
            for (int mi = 0; mi < 4; mi++)
                ldsm4(al[mi], base_al + (uint32_t)((wm * 64 + mi * 16 + a_r) * STR + ks * 16 + a_c) * 2);
            #pragma unroll
            for (int mi = 0; mi < 4; mi++)
                #pragma unroll
                for (int nj = 0; nj < 4; nj++) {
                    mma16816(c[mi][nj], ah[mi], &bh2[nj >> 1][(nj & 1) * 2]);
                    mma16816(c[mi][nj], ah[mi], &bl2[nj >> 1][(nj & 1) * 2]);
                    mma16816(c[mi][nj], al[mi], &bh2[nj >> 1][(nj & 1) * 2]);
                }
        }
        __syncthreads();
    }

    // epilogue
    #pragma unroll
    for (int mi = 0; mi < 4; mi++) {
        #pragma unroll
        for (int half = 0; half < 2; half++) {
            const int r = bm * 128 + wm * 64 + mi * 16 + (lane >> 2) + half * 8;
            #pragma unroll
            for (int nj = 0; nj < 4; nj++) {
                const int n = bn * 128 + wn * 32 + nj * 8 + (lane & 3) * 2;
                const float v0 = c[mi][nj][half * 2];
                const float v1 = c[mi][nj][half * 2 + 1];
                const float2 b2 = *(const float2*)(bias + n);
                if (EPI == 0) {
                    const int part = n >> 10, rr = n & 1023;
                    const int hh = rr >> 6, d = rr & 63;
                    const int bidx = r >> 11, srow = r & 2047;
                    const size_t off = ((size_t)((bidx * NHH + hh) * SS + srow)) * HDD + d;
                    if (part == 2) {
                        *(float2*)(g_v + off) = make_float2(v0 + b2.x, v1 + b2.y);
                    } else {
                        uint32_t hi, lo;
                        bsplit2(v0 + b2.x, v1 + b2.y, hi, lo);
                        __nv_bfloat16* dh = (part == 0) ? g_qh : g_kh;
                        __nv_bfloat16* dl = (part == 0) ? g_ql : g_kl;
                        *(uint32_t*)(dh + off) = hi;
                        *(uint32_t*)(dl + off) = lo;
                    }
                } else {
                    const float2 r2 = *(const float2*)(resid + (size_t)r * HH + n);
                    *(float2*)(outp + (size_t)r * HH + n) =
                        make_float2(v0 + b2.x + r2.x, v1 + b2.y + r2.y);
                }
            }
        }
    }
}

// ---------------- tensor-core flash attention, cp.async pipelined ----------------
#define QBYTES   (128 * ASTR * 2)                    // 18432 per operand
#define VBYTES   (64 * VSTR * 2)                     // 17408 per operand
#define KOFF     (2 * QBYTES)
#define VOFF     (KOFF + 4 * QBYTES)
#define ATTN2_SMEM (VOFF + 4 * VBYTES)               // 180224
__global__ __launch_bounds__(256) void attn_mma_kernel(const float* __restrict__ amask,
                                                       float* __restrict__ scores_out) {
    extern __shared__ __nv_bfloat16 smb[];
    const uint32_t sbase = smem_u32(smb);

    const int qt = 15 - blockIdx.x;
    const int hq = blockIdx.y;
    const int bb = blockIdx.z;
    const int tid = threadIdx.x, w = tid >> 5, lane = tid & 31;
    const int q0 = qt * 128;
    const int bh = bb * NHH + hq;

    const __nv_bfloat16* Qh_g = g_qh + (size_t)bh * SS * HDD;
    const __nv_bfloat16* Ql_g = g_ql + (size_t)bh * SS * HDD;
    const __nv_bfloat16* Kh_g = g_kh + (size_t)bh * SS * HDD;
    const __nv_bfloat16* Kl_g = g_kl + (size_t)bh * SS * HDD;
    const __nv_bfloat16* Vh_g = g_vth + (size_t)bh * HDD * SS;
    const __nv_bfloat16* Vl_g = g_vtl + (size_t)bh * HDD * SS;
    float* sc = scores_out + ((size_t)bh * SS + q0) * SS;
    const float* amk = amask + bb * SS;

    // ---- Q tile cp.async (once) ----
    #pragma unroll
    for (int op = 0; op < 2; op++) {
        const __nv_bfloat16* s = (op == 0 ? Qh_g : Ql_g) + (size_t)q0 * HDD;
        const uint32_t dbase = sbase + op * QBYTES;
        #pragma unroll
        for (int i = 0; i < 4; i++) {
            const int id = tid + i * 256;
            const int row = id >> 3, c16 = id & 7;
            CPA(dbase + (uint32_t)(row * ASTR + c16 * 8) * 2, s + (size_t)row * HDD + c16 * 8);
        }
    }
    auto loadKV = [&](int buf, int k0) {
        #pragma unroll
        for (int op = 0; op < 2; op++) {
            const __nv_bfloat16* s = (op == 0 ? Kh_g : Kl_g) + (size_t)k0 * HDD;
            const uint32_t dbase = sbase + KOFF + (buf * 2 + op) * QBYTES;
            #pragma unroll
            for (int i = 0; i < 4; i++) {
                const int id = tid + i * 256;
                const int row = id >> 3, c16 = id & 7;
                CPA(dbase + (uint32_t)(row * ASTR + c16 * 8) * 2, s + (size_t)row * HDD + c16 * 8);
            }
        }
        #pragma unroll
        for (int op = 0; op < 2; op++) {
            const __nv_bfloat16* s = (op == 0 ? Vh_g : Vl_g) + k0;
            const uint32_t dbase = sbase + VOFF + (buf * 2 + op) * VBYTES;
            #pragma unroll
            for (int i = 0; i < 4; i++) {
                const int id = tid + i * 256;
                const int row = id >> 4, c16 = id & 15;
                CPA(dbase + (uint32_t)(row * VSTR + c16 * 8) * 2, s + (size_t)row * SS + c16 * 8);
            }
        }
    };
    loadKV(0, 0); CPC();

    float ctx[8][4];
    #pragma unroll
    for (int j = 0; j < 8; j++)
        #pragma unroll
        for (int q = 0; q < 4; q++) ctx[j][q] = 0.f;
    float mrow1 = -1e30f, mrow2 = -1e30f, lsum1 = 0.f, lsum2 = 0.f;

    const int a_r = lane & 15, a_c = (lane >> 4) * 8;
    const int b_r = ((lane >> 4) << 3) + (lane & 7), b_c = ((lane >> 3) & 1) * 8;
    const int colb = (lane & 3) * 2;
    const int rt1 = w * 16 + (lane >> 2), rt2 = rt1 + 8;
    const int qg1 = q0 + rt1, qg2 = q0 + rt2;

    uint32_t Qfh[4][4], Qfl[4][4];

    for (int kt = 0; kt <= qt; kt++) {
        const int k0 = kt * 128;
        CPW0();
        __syncthreads();
        if (kt == 0) {
            #pragma unroll
            for (int kg = 0; kg < 4; kg++) {
                ldsm4(Qfh[kg], sbase + (uint32_t)((w * 16 + a_r) * ASTR + kg * 16 + a_c) * 2);
                ldsm4(Qfl[kg], sbase + QBYTES + (uint32_t)((w * 16 + a_r) * ASTR + kg * 16 + a_c) * 2);
            }
        }
        if (kt + 1 <= qt) { loadKV((kt + 1) & 1, (kt + 1) * 128); CPC(); }

        const int buf = kt & 1;
        const uint32_t khb = sbase + KOFF + (buf * 2 + 0) * QBYTES;
        const uint32_t klb = sbase + KOFF + (buf * 2 + 1) * QBYTES;
        const uint32_t vhb = sbase + VOFF + (buf * 2 + 0) * VBYTES;
        const uint32_t vlb = sbase + VOFF + (buf * 2 + 1) * VBYTES;

        // ---- S = Q K^T (3-term split) ----
        float S[16][4];
        #pragma unroll
        for (int j = 0; j < 16; j++)
            #pragma unroll
            for (int q = 0; q < 4; q++) S[j][q] = 0.f;
        #pragma unroll
        for (int kg = 0; kg < 4; kg++) {
            #pragma unroll
            for (int pj = 0; pj < 8; pj++) {
                const uint32_t off = (uint32_t)((pj * 16 + b_r) * ASTR + kg * 16 + b_c) * 2;
                uint32_t bh4[4], bl4[4];
                ldsm4(bh4, khb + off);
                ldsm4(bl4, klb + off);
                mma16816(S[2 * pj],     Qfh[kg], &bh4[0]);
                mma16816(S[2 * pj],     Qfh[kg], &bl4[0]);
                mma16816(S[2 * pj],     Qfl[kg], &bh4[0]);
                mma16816(S[2 * pj + 1], Qfh[kg], &bh4[2]);
                mma16816(S[2 * pj + 1], Qfh[kg], &bl4[2]);
                mma16816(S[2 * pj + 1], Qfl[kg], &bh4[2]);
            }
        }

        // ---- scale, causal, amask, emit raw scores ----
        const bool diag = (kt == qt);
        #pragma unroll
        for (int j = 0; j < 16; j++) {
            const int c0 = k0 + j * 8 + colb;
            const float2 am2 = *(const float2*)(amk + c0);
            const float mk0 = am2.x * -10000.f, mk1 = am2.y * -10000.f;
            float s0 = fmaf(S[j][0], 0.125f, mk0);
            float s1 = fmaf(S[j][1], 0.125f, mk1);
            float s2 = fmaf(S[j][2], 0.125f, mk0);
            float s3 = fmaf(S[j][3], 0.125f, mk1);
            if (diag) {
                if (c0     > qg1) s0 = -10000.f + mk0;
                if (c0 + 1 > qg1) s1 = -10000.f + mk1;
                if (c0     > qg2) s2 = -10000.f + mk0;
                if (c0 + 1 > qg2) s3 = -10000.f + mk1;
            }
            *(float2*)(sc + (size_t)rt1 * SS + c0) = make_float2(s0, s1);
            *(float2*)(sc + (size_t)rt2 * SS + c0) = make_float2(s2, s3);
            S[j][0] = s0; S[j][1] = s1; S[j][2] = s2; S[j][3] = s3;
        }

        // ---- online softmax ----
        float mx1 = -1e30f, mx2 = -1e30f;
        #pragma unroll
        for (int j = 0; j < 16; j++) {
            mx1 = fmaxf(mx1, fmaxf(S[j][0], S[j][1]));
            mx2 = fmaxf(mx2, fmaxf(S[j][2], S[j][3]));
        }
        mx1 = fmaxf(mx1, __shfl_xor_sync(0xffffffffu, mx1, 1));
        mx1 = fmaxf(mx1, __shfl_xor_sync(0xffffffffu, mx1, 2));
        mx2 = fmaxf(mx2, __shfl_xor_sync(0xffffffffu, mx2, 1));
        mx2 = fmaxf(mx2, __shfl_xor_sync(0xffffffffu, mx2, 2));
        const float mn1 = fmaxf(mrow1, mx1), mn2 = fmaxf(mrow2, mx2);
        const float al1 = fexp(mrow1 - mn1), al2 = fexp(mrow2 - mn2);
        float sum1 = 0.f, sum2 = 0.f;
        #pragma unroll
        for (int j = 0; j < 16; j++) {
            S[j][0] = fexp(S[j][0] - mn1);
            S[j][1] = fexp(S[j][1] - mn1);
            S[j][2] = fexp(S[j][2] - mn2);
            S[j][3] = fexp(S[j][3] - mn2);
            sum1 += S[j][0] + S[j][1];
            sum2 += S[j][2] + S[j][3];
        }
        sum1 += __shfl_xor_sync(0xffffffffu, sum1, 1);
        sum1 += __shfl_xor_sync(0xffffffffu, sum1, 2);
        sum2 += __shfl_xor_sync(0xffffffffu, sum2, 1);
        sum2 += __shfl_xor_sync(0xffffffffu, sum2, 2);
        lsum1 = lsum1 * al1 + sum1; mrow1 = mn1;
        lsum2 = lsum2 * al2 + sum2; mrow2 = mn2;
        #pragma unroll
        for (int j = 0; j < 8; j++) {
            ctx[j][0] *= al1; ctx[j][1] *= al1;
            ctx[j][2] *= al2; ctx[j][3] *= al2;
        }

        // ---- ctx += P V (P in registers, 3-term split) ----
        #pragma unroll
        for (int kg = 0; kg < 8; kg++) {
            uint32_t ah[4], alr[4];
            bsplit2(S[2 * kg][0],     S[2 * kg][1],     ah[0], alr[0]);
            bsplit2(S[2 * kg][2],     S[2 * kg][3],     ah[1], alr[1]);
            bsplit2(S[2 * kg + 1][0], S[2 * kg + 1][1], ah[2], alr[2]);
            bsplit2(S[2 * kg + 1][2], S[2 * kg + 1][3], ah[3], alr[3]);
            #pragma unroll
            for (int pj = 0; pj < 4; pj++) {
                const uint32_t off = (uint32_t)((pj * 16 + b_r) * VSTR + kg * 16 + b_c) * 2;
                uint32_t bh4[4], bl4[4];
                ldsm4(bh4, vhb + off);
                ldsm4(bl4, vlb + off);
                mma16816(ctx[2 * pj],     ah,  &bh4[0]);
                mma16816(ctx[2 * pj],     alr, &bh4[0]);
                mma16816(ctx[2 * pj],     ah,  &bl4[0]);
                mma16816(ctx[2 * pj + 1], ah,  &bh4[2]);
                mma16816(ctx[2 * pj + 1], alr, &bh4[2]);
                mma16816(ctx[2 * pj + 1], ah,  &bl4[2]);
            }
        }
        __syncthreads();
    }

    // ---- tail tiles: fully causal-masked scores fill ----
    {
        const int r = tid >> 1, ch0 = (tid & 1) * 64;
        for (int kt2 = qt + 1; kt2 < 16; kt2++) {
            const int k0 = kt2 * 128;
            #pragma unroll
            for (int i = 0; i < 16; i++) {
                const int cc = ch0 + i * 4;
                const float4 a4 = *(const float4*)(amk + k0 + cc);
                const float4 val = make_float4(-10000.f + a4.x * -10000.f,
                                               -10000.f + a4.y * -10000.f,
                                               -10000.f + a4.z * -10000.f,
                                               -10000.f + a4.w * -10000.f);
                *(float4*)(sc + (size_t)r * SS + k0 + cc) = val;
            }
        }
    }

    // ---- ctx /= lsum -> bf16 hi/lo ----
    const float inv1 = 1.0f / lsum1, inv2 = 1.0f / lsum2;
    #pragma unroll
    for (int j = 0; j < 8; j++) {
        const int d = hq * 64 + j * 8 + colb;
        const size_t o1 = ((size_t)(bb * SS) + q0 + rt1) * HH + d;
        const size_t o2 = ((size_t)(bb * SS) + q0 + rt2) * HH + d;
        uint32_t hi, lo;
        bsplit2(ctx[j][0] * inv1, ctx[j][1] * inv1, hi, lo);
        *(uint32_t*)(g_ch + o1) = hi;
        *(uint32_t*)(g_cl + o1) = lo;
        bsplit2(ctx[j][2] * inv2, ctx[j][3] * inv2, hi, lo);
        *(uint32_t*)(g_ch + o2) = hi;
        *(uint32_t*)(g_cl + o2) = lo;
    }
}

// ---------------- launch ----------------
extern "C" void kernel_launch(void* const* d_in, const int* in_sizes, int n_in,
                              void* d_out, int out_size) {
    const float* hs       = (const float*)d_in[0];
    const float* amask    = (const float*)d_in[1];
    const float* c_attn_w = (const float*)d_in[2];
    const float* c_attn_b = (const float*)d_in[3];
    const float* c_proj_w = (const float*)d_in[4];
    const float* c_proj_b = (const float*)d_in[5];
    const float* ln_g     = (const float*)d_in[6];
    const float* ln_b     = (const float*)d_in[7];
    float* out = (float*)d_out;
    float* scores = out + (size_t)MM * HH;

    __nv_bfloat16 *xh, *xl, *wqh, *wql, *wph, *wpl, *ch, *cl;
    cudaGetSymbolAddress((void**)&xh,  g_xh);
    cudaGetSymbolAddress((void**)&xl,  g_xl);
    cudaGetSymbolAddress((void**)&wqh, g_wqh);
    cudaGetSymbolAddress((void**)&wql, g_wql);
    cudaGetSymbolAddress((void**)&wph, g_wph);
    cudaGetSymbolAddress((void**)&wpl, g_wpl);
    cudaGetSymbolAddress((void**)&ch,  g_ch);
    cudaGetSymbolAddress((void**)&cl,  g_cl);

    cudaFuncSetAttribute(mma_gemm_kernel<0>, cudaFuncAttributeMaxDynamicSharedMemorySize, MMA_SMEM);
    cudaFuncSetAttribute(mma_gemm_kernel<1>, cudaFuncAttributeMaxDynamicSharedMemorySize, MMA_SMEM);
    cudaFuncSetAttribute(attn_mma_kernel, cudaFuncAttributeMaxDynamicSharedMemorySize, ATTN2_SMEM);

    ln_kernel<<<MM, 256>>>(hs, ln_g, ln_b);
    wsplit_kernel<<<dim3(N3 / 32, KK / 32), 256>>>(c_attn_w, wqh, wql, N3);
    wsplit_kernel<<<dim3(HH / 32, KK / 32), 256>>>(c_proj_w, wph, wpl, HH);
    mma_gemm_kernel<0><<<dim3(N3 / 128, MM / 128), 256, MMA_SMEM>>>(
        xh, xl, wqh, wql, c_attn_b, nullptr, nullptr);
    vtrans_kernel<<<dim3(SS / 32, HDD / 32, BB * NHH), 256>>>();
    attn_mma_kernel<<<dim3(16, NHH, BB), 256, ATTN2_SMEM>>>(amask, scores);
    mma_gemm_kernel<1><<<dim3(HH / 128, MM / 128), 256, MMA_SMEM>>>(
        ch, cl, wph, wpl, c_proj_b, hs, out);
}

// round 14
// speedup vs baseline: 1.5525x; 1.0000x over previous
#include <cuda_runtime.h>
#include <cuda_bf16.h>
#include <cstdint>

#define BB   4
#define SS   2048
#define HH   1024
#define NHH  16
#define HDD  64
#define MM   (BB*SS)      // 8192
#define N3   (3*HH)       // 3072
#define KK   1024
#define STR  40           // gemm smem row stride in bf16 (80B, 16B-aligned, conflict-free)
#define ASTR 72           // attn Q/K smem stride in bf16 (144B)
#define VSTR 136          // attn V^T smem stride in bf16 (272B)

// ---------------- helpers ----------------
__device__ __forceinline__ uint32_t smem_u32(const void* p) {
    uint32_t a;
    asm("{ .reg .u64 t; cvta.to.shared.u64 t, %1; cvt.u32.u64 %0, t; }" : "=r"(a) : "l"(p));
    return a;
}
__device__ __forceinline__ void ldsm4(uint32_t* r, uint32_t addr) {
    asm volatile("ldmatrix.sync.aligned.m8n8.x4.shared.b16 {%0,%1,%2,%3}, [%4];"
        : "=r"(r[0]), "=r"(r[1]), "=r"(r[2]), "=r"(r[3]) : "r"(addr));
}
__device__ __forceinline__ void mma16816(float* c, const uint32_t* a, const uint32_t* b) {
    asm volatile("mma.sync.aligned.m16n8k16.row.col.f32.bf16.bf16.f32 "
        "{%0,%1,%2,%3}, {%4,%5,%6,%7}, {%8,%9}, {%0,%1,%2,%3};"
        : "+f"(c[0]), "+f"(c[1]), "+f"(c[2]), "+f"(c[3])
        : "r"(a[0]), "r"(a[1]), "r"(a[2]), "r"(a[3]), "r"(b[0]), "r"(b[1]));
}
#define CPA(dst, src) asm volatile("cp.async.cg.shared.global [%0], [%1], 16;" :: "r"(dst), "l"(src))
#define CPC() asm volatile("cp.async.commit_group;" ::: "memory")
#define CPW0() asm volatile("cp.async.wait_group 0;" ::: "memory")

// fast exp on the FMA pipe (no MUFU)
__device__ __forceinline__ float fexp(float x) {
    float y = x * 1.4426950408889634f;
    y = fmaxf(y, -120.0f);
    const float SH = 12582912.0f;
    float z = y + SH;
    int n = __float_as_int(z) - 0x4B400000;
    float f = y - (z - SH);
    float p = 1.3333558146e-3f;
    p = fmaf(p, f, 9.6181291076e-3f);
    p = fmaf(p, f, 5.5504108665e-2f);
    p = fmaf(p, f, 2.4022650696e-1f);
    p = fmaf(p, f, 6.9314718056e-1f);
    p = fmaf(p, f, 1.0f);
    return __int_as_float(__float_as_int(p) + (n << 23));
}
__device__ __forceinline__ void bsplit2(float x, float y, uint32_t& hi, uint32_t& lo) {
    __nv_bfloat16 hx = __float2bfloat16(x);
    __nv_bfloat16 hy = __float2bfloat16(y);
    __nv_bfloat162 H(hx, hy);
    __nv_bfloat162 L(__float2bfloat16(x - __bfloat162float(hx)),
                     __float2bfloat16(y - __bfloat162float(hy)));
    hi = *reinterpret_cast<uint32_t*>(&H);
    lo = *reinterpret_cast<uint32_t*>(&L);
}

// ---------------- scratch ----------------
__device__ __align__(128) __nv_bfloat16 g_xh[(size_t)MM * KK];
__device__ __align__(128) __nv_bfloat16 g_xl[(size_t)MM * KK];
__device__ __align__(128) __nv_bfloat16 g_wqh[(size_t)N3 * KK];
__device__ __align__(128) __nv_bfloat16 g_wql[(size_t)N3 * KK];
__device__ __align__(128) __nv_bfloat16 g_wph[(size_t)HH * KK];
__device__ __align__(128) __nv_bfloat16 g_wpl[(size_t)HH * KK];
__device__ __align__(128) __nv_bfloat16 g_ch[(size_t)MM * HH];
__device__ __align__(128) __nv_bfloat16 g_cl[(size_t)MM * HH];
__device__ __align__(128) __nv_bfloat16 g_qh[(size_t)BB * NHH * SS * HDD];  // [b,h,s,d]
__device__ __align__(128) __nv_bfloat16 g_ql[(size_t)BB * NHH * SS * HDD];
__device__ __align__(128) __nv_bfloat16 g_kh[(size_t)BB * NHH * SS * HDD];
__device__ __align__(128) __nv_bfloat16 g_kl[(size_t)BB * NHH * SS * HDD];
__device__ __align__(128) __nv_bfloat16 g_vth[(size_t)BB * NHH * HDD * SS]; // [b,h,d,s]
__device__ __align__(128) __nv_bfloat16 g_vtl[(size_t)BB * NHH * HDD * SS];
__device__ float g_v[(size_t)BB * NHH * SS * HDD];                          // [b,h,s,d] fp32

// ---------------- layernorm + split ----------------
__global__ __launch_bounds__(256) void ln_kernel(const float* __restrict__ hs,
                                                 const float* __restrict__ gamma,
                                                 const float* __restrict__ beta) {
    const int row = blockIdx.x;
    const int tid = threadIdx.x;
    const float4 v = ((const float4*)(hs + (size_t)row * HH))[tid];
    float s  = v.x + v.y + v.z + v.w;
    float s2 = v.x*v.x + v.y*v.y + v.z*v.z + v.w*v.w;
    #pragma unroll
    for (int o = 16; o > 0; o >>= 1) {
        s  += __shfl_xor_sync(0xffffffffu, s,  o);
        s2 += __shfl_xor_sync(0xffffffffu, s2, o);
    }
    __shared__ float red[2][8];
    const int wid = tid >> 5, lane = tid & 31;
    if (lane == 0) { red[0][wid] = s; red[1][wid] = s2; }
    __syncthreads();
    float mean = 0.f, msq = 0.f;
    #pragma unroll
    for (int i = 0; i < 8; i++) { mean += red[0][i]; msq += red[1][i]; }
    mean *= (1.0f / HH);
    msq  *= (1.0f / HH);
    const float rstd = rsqrtf(msq - mean * mean + 1e-5f);
    const float4 g = ((const float4*)gamma)[tid];
    const float4 b = ((const float4*)beta)[tid];
    float o[4];
    o[0] = (v.x - mean) * rstd * g.x + b.x;
    o[1] = (v.y - mean) * rstd * g.y + b.y;
    o[2] = (v.z - mean) * rstd * g.z + b.z;
    o[3] = (v.w - mean) * rstd * g.w + b.w;
    const size_t off = (size_t)row * HH + tid * 4;
    uint32_t h0, l0, h1, l1;
    bsplit2(o[0], o[1], h0, l0);
    bsplit2(o[2], o[3], h1, l1);
    *(uint32_t*)(g_xh + off)     = h0;
    *(uint32_t*)(g_xh + off + 2) = h1;
    *(uint32_t*)(g_xl + off)     = l0;
    *(uint32_t*)(g_xl + off + 2) = l1;
}

// ---------------- weight transpose + split ----------------
__global__ __launch_bounds__(256) void wsplit_kernel(const float* __restrict__ W,
                                                     __nv_bfloat16* __restrict__ Th,
                                                     __nv_bfloat16* __restrict__ Tl,
                                                     int N) {
    __shared__ float sm[32][33];
    const int n0 = blockIdx.x * 32, k0 = blockIdx.y * 32;
    const int tx = threadIdx.x & 31, ty = threadIdx.x >> 5;
    #pragma unroll
    for (int i = 0; i < 4; i++) {
        const int k = ty * 4 + i;
        sm[k][tx] = W[(size_t)(k0 + k) * N + n0 + tx];
    }
    __syncthreads();
    #pragma unroll
    for (int i = 0; i < 4; i++) {
        const int n = ty * 4 + i;
        const float v = sm[tx][n];
        const __nv_bfloat16 h = __float2bfloat16(v);
        const __nv_bfloat16 l = __float2bfloat16(v - __bfloat162float(h));
        Th[(size_t)(n0 + n) * KK + k0 + tx] = h;
        Tl[(size_t)(n0 + n) * KK + k0 + tx] = l;
    }
}

// ---------------- V transpose + split: g_v[bh][s][d] -> g_vth/g_vtl [bh][d][s] ----
__global__ __launch_bounds__(256) void vtrans_kernel() {
    __shared__ float sm[32][33];
    const int s0 = blockIdx.x * 32, d0 = blockIdx.y * 32;
    const int bh = blockIdx.z;
    const int tx = threadIdx.x & 31, ty = threadIdx.x >> 5;
    const float* src = g_v + ((size_t)bh * SS) * HDD;
    #pragma unroll
    for (int i = 0; i < 4; i++) {
        const int k = ty * 4 + i;
        sm[k][tx] = src[(size_t)(s0 + k) * HDD + d0 + tx];
    }
    __syncthreads();
    #pragma unroll
    for (int i = 0; i < 4; i++) {
        const int n = ty * 4 + i;           // d within tile
        const float v = sm[tx][n];          // s = tx
        const __nv_bfloat16 h = __float2bfloat16(v);
        const __nv_bfloat16 l = __float2bfloat16(v - __bfloat162float(h));
        const size_t off = ((size_t)bh * HDD + d0 + n) * SS + s0 + tx;
        g_vth[off] = h;
        g_vtl[off] = l;
    }
}

// ---------------- split-bf16 mma.sync GEMM, cp.async pipelined ----------------
#define MMA_SMEM (8 * 128 * STR * 2)
template<int EPI>
__global__ __launch_bounds__(256) void mma_gemm_kernel(
    const __nv_bfloat16* __restrict__ Ah, const __nv_bfloat16* __restrict__ Al,
    const __nv_bfloat16* __restrict__ Bh, const __nv_bfloat16* __restrict__ Bl,
    const float* __restrict__ bias, const float* __restrict__ resid,
    float* __restrict__ outp)
{
    extern __shared__ __nv_bfloat16 smb[];
    const int tid = threadIdx.x, wid = tid >> 5, lane = tid & 31;
    const int bm = blockIdx.y, bn = blockIdx.x;
    const int wm = wid >> 2, wn = wid & 3;
    const uint32_t sbase = smem_u32(smb);

    const __nv_bfloat16* srcs[4] = {Ah + (size_t)bm * 128 * KK, Al + (size_t)bm * 128 * KK,
                                    Bh + (size_t)bn * 128 * KK, Bl + (size_t)bn * 128 * KK};

    float c[4][4][4];
    #pragma unroll
    for (int i = 0; i < 4; i++)
        #pragma unroll
        for (int j = 0; j < 4; j++)
            #pragma unroll
            for (int q = 0; q < 4; q++) c[i][j][q] = 0.f;

    auto cpload = [&](int buf, int k0) {
        #pragma unroll
        for (int op = 0; op < 4; op++) {
            const __nv_bfloat16* s = srcs[op] + k0;
            const uint32_t dbase = sbase + (uint32_t)((buf * 4 + op) * 128 * STR) * 2;
            #pragma unroll
            for (int i = 0; i < 2; i++) {
                const int id = tid + i * 256;
                const int row = id >> 2, c16 = id & 3;
                CPA(dbase + (uint32_t)(row * STR + c16 * 8) * 2,
                    s + (size_t)row * KK + c16 * 8);
            }
        }
    };
    cpload(0, 0); CPC();

    const int a_r = lane & 15, a_c = (lane >> 4) * 8;
    const int b_r = ((lane >> 4) << 3) + (lane & 7), b_c = ((lane >> 3) & 1) * 8;

    const int NCH = KK / 32;
    for (int ch = 0; ch < NCH; ch++) {
        CPW0();
        __syncthreads();
        if (ch + 1 < NCH) { cpload((ch + 1) & 1, (ch + 1) * 32); CPC(); }
        const int buf = ch & 1;
        const uint32_t base_ah = sbase + (uint32_t)((buf * 4 + 0) * 128 * STR) * 2;
        const uint32_t base_al = sbase + (uint32_t)((buf * 4 + 1) * 128 * STR) * 2;
        const uint32_t base_bh = sbase + (uint32_t)((buf * 4 + 2) * 128 * STR) * 2;
        const uint32_t base_bl = sbase + (uint32_t)((buf * 4 + 3) * 128 * STR) * 2;
        #pragma unroll
        for (int ks = 0; ks < 2; ks++) {
            uint32_t ah[4][4], al[4][4], bh2[2][4], bl2[2][4];
            #pragma unroll
            for (int mi = 0; mi < 4; mi++)
                ldsm4(ah[mi], base_ah + (uint32_t)((wm * 64 + mi * 16 + a_r) * STR + ks * 16 + a_c) * 2);
            #pragma unroll
            for (int pj = 0; pj < 2; pj++)
                ldsm4(bh2[pj], base_bh + (uint32_t)((wn * 32 + pj * 16 + b_r) * STR + ks * 16 + b_c) * 2);
            #pragma unroll
            for (int pj = 0; pj < 2; pj++)
                ldsm4(bl2[pj], base_bl + (uint32_t)((wn * 32 + pj * 16 + b_r) * STR + ks * 16 + b_c) * 2);
            #pragma unroll
            for (int mi = 0; mi < 4; mi++)
                ldsm4(al[mi], base_al + (uint32_t)((wm * 64 + mi * 16 + a_r) * STR + ks * 16 + a_c) * 2);
            #pragma unroll
            for (int mi = 0; mi < 4; mi++)
                #pragma unroll
                for (int nj = 0; nj < 4; nj++) {
                    mma16816(c[mi][nj], ah[mi], &bh2[nj >> 1][(nj & 1) * 2]);
                    mma16816(c[mi][nj], ah[mi], &bl2[nj >> 1][(nj & 1) * 2]);
                    mma16816(c[mi][nj], al[mi], &bh2[nj >> 1][(nj & 1) * 2]);
                }
        }
        __syncthreads();
    }

    // epilogue
    #pragma unroll
    for (int mi = 0; mi < 4; mi++) {
        #pragma unroll
        for (int half = 0; half < 2; half++) {
            const int r = bm * 128 + wm * 64 + mi * 16 + (lane >> 2) + half * 8;
            #pragma unroll
            for (int nj = 0; nj < 4; nj++) {
                const int n = bn * 128 + wn * 32 + nj * 8 + (lane & 3) * 2;
                const float v0 = c[mi][nj][half * 2];
                const float v1 = c[mi][nj][half * 2 + 1];
                const float2 b2 = *(const float2*)(bias + n);
                if (EPI == 0) {
                    const int part = n >> 10, rr = n & 1023;
                    const int hh = rr >> 6, d = rr & 63;
                    const int bidx = r >> 11, srow = r & 2047;
                    const size_t off = ((size_t)((bidx * NHH + hh) * SS + srow)) * HDD + d;
                    if (part == 2) {
                        *(float2*)(g_v + off) = make_float2(v0 + b2.x, v1 + b2.y);
                    } else {
                        uint32_t hi, lo;
                        bsplit2(v0 + b2.x, v1 + b2.y, hi, lo);
                        __nv_bfloat16* dh = (part == 0) ? g_qh : g_kh;
                        __nv_bfloat16* dl = (part == 0) ? g_ql : g_kl;
                        *(uint32_t*)(dh + off) = hi;
                        *(uint32_t*)(dl + off) = lo;
                    }
                } else {
                    const float2 r2 = *(const float2*)(resid + (size_t)r * HH + n);
                    *(float2*)(outp + (size_t)r * HH + n) =
                        make_float2(v0 + b2.x + r2.x, v1 + b2.y + r2.y);
                }
            }
        }
    }
}

// ---------------- tensor-core flash attention, cp.async pipelined ----------------
#define QBYTES   (128 * ASTR * 2)                    // 18432 per operand
#define VBYTES   (64 * VSTR * 2)                     // 17408 per operand
#define KOFF     (2 * QBYTES)
#define VOFF     (KOFF + 4 * QBYTES)
#define ATTN2_SMEM (VOFF + 4 * VBYTES)               // 180224
__global__ __launch_bounds__(256) void attn_mma_kernel(const float* __restrict__ amask,
                                                       float* __restrict__ scores_out) {
    extern __shared__ __nv_bfloat16 smb[];
    const uint32_t sbase = smem_u32(smb);

    const int qt = 15 - blockIdx.x;
    const int hq = blockIdx.y;
    const int bb = blockIdx.z;
    const int tid = threadIdx.x, w = tid >> 5, lane = tid & 31;
    const int q0 = qt * 128;
    const int bh = bb * NHH + hq;

    const __nv_bfloat16* Qh_g = g_qh + (size_t)bh * SS * HDD;
    const __nv_bfloat16* Ql_g = g_ql + (size_t)bh * SS * HDD;
    const __nv_bfloat16* Kh_g = g_kh + (size_t)bh * SS * HDD;
    const __nv_bfloat16* Kl_g = g_kl + (size_t)bh * SS * HDD;
    const __nv_bfloat16* Vh_g = g_vth + (size_t)bh * HDD * SS;
    const __nv_bfloat16* Vl_g = g_vtl + (size_t)bh * HDD * SS;
    float* sc = scores_out + ((size_t)bh * SS + q0) * SS;
    const float* amk = amask + bb * SS;

    // ---- Q tile cp.async (once) ----
    #pragma unroll
    for (int op = 0; op < 2; op++) {
        const __nv_bfloat16* s = (op == 0 ? Qh_g : Ql_g) + (size_t)q0 * HDD;
        const uint32_t dbase = sbase + op * QBYTES;
        #pragma unroll
        for (int i = 0; i < 4; i++) {
            const int id = tid + i * 256;
            const int row = id >> 3, c16 = id & 7;
            CPA(dbase + (uint32_t)(row * ASTR + c16 * 8) * 2, s + (size_t)row * HDD + c16 * 8);
        }
    }
    auto loadKV = [&](int buf, int k0) {
        #pragma unroll
        for (int op = 0; op < 2; op++) {
            const __nv_bfloat16* s = (op == 0 ? Kh_g : Kl_g) + (size_t)k0 * HDD;
            const uint32_t dbase = sbase + KOFF + (buf * 2 + op) * QBYTES;
            #pragma unroll
            for (int i = 0; i < 4; i++) {
                const int id = tid + i * 256;
                const int row = id >> 3, c16 = id & 7;
                CPA(dbase + (uint32_t)(row * ASTR + c16 * 8) * 2, s + (size_t)row * HDD + c16 * 8);
            }
        }
        #pragma unroll
        for (int op = 0; op < 2; op++) {
            const __nv_bfloat16* s = (op == 0 ? Vh_g : Vl_g) + k0;
            const uint32_t dbase = sbase + VOFF + (buf * 2 + op) * VBYTES;
            #pragma unroll
            for (int i = 0; i < 4; i++) {
                const int id = tid + i * 256;
                const int row = id >> 4, c16 = id & 15;
                CPA(dbase + (uint32_t)(row * VSTR + c16 * 8) * 2, s + (size_t)row * SS + c16 * 8);
            }
        }
    };
    loadKV(0, 0); CPC();

    float ctx[8][4];
    #pragma unroll
    for (int j = 0; j < 8; j++)
        #pragma unroll
        for (int q = 0; q < 4; q++) ctx[j][q] = 0.f;
    float mrow1 = -1e30f, mrow2 = -1e30f, lsum1 = 0.f, lsum2 = 0.f;

    const int a_r = lane & 15, a_c = (lane >> 4) * 8;
    const int b_r = ((lane >> 4) << 3) + (lane & 7), b_c = ((lane >> 3) & 1) * 8;
    const int colb = (lane & 3) * 2;
    const int rt1 = w * 16 + (lane >> 2), rt2 = rt1 + 8;
    const int qg1 = q0 + rt1, qg2 = q0 + rt2;

    uint32_t Qfh[4][4], Qfl[4][4];

    for (int kt = 0; kt <= qt; kt++) {
        const int k0 = kt * 128;
        CPW0();
        __syncthreads();
        if (kt == 0) {
            #pragma unroll
            for (int kg = 0; kg < 4; kg++) {
                ldsm4(Qfh[kg], sbase + (uint32_t)((w * 16 + a_r) * ASTR + kg * 16 + a_c) * 2);
                ldsm4(Qfl[kg], sbase + QBYTES + (uint32_t)((w * 16 + a_r) * ASTR + kg * 16 + a_c) * 2);
            }
        }
        if (kt + 1 <= qt) { loadKV((kt + 1) & 1, (kt + 1) * 128); CPC(); }

        const int buf = kt & 1;
        const uint32_t khb = sbase + KOFF + (buf * 2 + 0) * QBYTES;
        const uint32_t klb = sbase + KOFF + (buf * 2 + 1) * QBYTES;
        const uint32_t vhb = sbase + VOFF + (buf * 2 + 0) * VBYTES;
        const uint32_t vlb = sbase + VOFF + (buf * 2 + 1) * VBYTES;

        // ---- S = Q K^T (3-term split) ----
        float S[16][4];
        #pragma unroll
        for (int j = 0; j < 16; j++)
            #pragma unroll
            for (int q = 0; q < 4; q++) S[j][q] = 0.f;
        #pragma unroll
        for (int kg = 0; kg < 4; kg++) {
            #pragma unroll
            for (int pj = 0; pj < 8; pj++) {
                const uint32_t off = (uint32_t)((pj * 16 + b_r) * ASTR + kg * 16 + b_c) * 2;
                uint32_t bh4[4], bl4[4];
                ldsm4(bh4, khb + off);
                ldsm4(bl4, klb + off);
                mma16816(S[2 * pj],     Qfh[kg], &bh4[0]);
                mma16816(S[2 * pj],     Qfh[kg], &bl4[0]);
                mma16816(S[2 * pj],     Qfl[kg], &bh4[0]);
                mma16816(S[2 * pj + 1], Qfh[kg], &bh4[2]);
                mma16816(S[2 * pj + 1], Qfh[kg], &bl4[2]);
                mma16816(S[2 * pj + 1], Qfl[kg], &bh4[2]);
            }
        }

        // ---- scale, causal, amask, emit raw scores ----
        const bool diag = (kt == qt);
        #pragma unroll
        for (int j = 0; j < 16; j++) {
            const int c0 = k0 + j * 8 + colb;
            const float2 am2 = *(const float2*)(amk + c0);
            const float mk0 = am2.x * -10000.f, mk1 = am2.y * -10000.f;
            float s0 = fmaf(S[j][0], 0.125f, mk0);
            float s1 = fmaf(S[j][1], 0.125f, mk1);
            float s2 = fmaf(S[j][2], 0.125f, mk0);
            float s3 = fmaf(S[j][3], 0.125f, mk1);
            if (diag) {
                if (c0     > qg1) s0 = -10000.f + mk0;
                if (c0 + 1 > qg1) s1 = -10000.f + mk1;
                if (c0     > qg2) s2 = -10000.f + mk0;
                if (c0 + 1 > qg2) s3 = -10000.f + mk1;
            }
            *(float2*)(sc + (size_t)rt1 * SS + c0) = make_float2(s0, s1);
            *(float2*)(sc + (size_t)rt2 * SS + c0) = make_float2(s2, s3);
            S[j][0] = s0; S[j][1] = s1; S[j][2] = s2; S[j][3] = s3;
        }

        // ---- online softmax ----
        float mx1 = -1e30f, mx2 = -1e30f;
        #pragma unroll
        for (int j = 0; j < 16; j++) {
            mx1 = fmaxf(mx1, fmaxf(S[j][0], S[j][1]));
            mx2 = fmaxf(mx2, fmaxf(S[j][2], S[j][3]));
        }
        mx1 = fmaxf(mx1, __shfl_xor_sync(0xffffffffu, mx1, 1));
        mx1 = fmaxf(mx1, __shfl_xor_sync(0xffffffffu, mx1, 2));
        mx2 = fmaxf(mx2, __shfl_xor_sync(0xffffffffu, mx2, 1));
        mx2 = fmaxf(mx2, __shfl_xor_sync(0xffffffffu, mx2, 2));
        const float mn1 = fmaxf(mrow1, mx1), mn2 = fmaxf(mrow2, mx2);
        const float al1 = fexp(mrow1 - mn1), al2 = fexp(mrow2 - mn2);
        float sum1 = 0.f, sum2 = 0.f;
        #pragma unroll
        for (int j = 0; j < 16; j++) {
            S[j][0] = fexp(S[j][0] - mn1);
            S[j][1] = fexp(S[j][1] - mn1);
            S[j][2] = fexp(S[j][2] - mn2);
            S[j][3] = fexp(S[j][3] - mn2);
            sum1 += S[j][0] + S[j][1];
            sum2 += S[j][2] + S[j][3];
        }
        sum1 += __shfl_xor_sync(0xffffffffu, sum1, 1);
        sum1 += __shfl_xor_sync(0xffffffffu, sum1, 2);
        sum2 += __shfl_xor_sync(0xffffffffu, sum2, 1);
        sum2 += __shfl_xor_sync(0xffffffffu, sum2, 2);
        lsum1 = lsum1 * al1 + sum1; mrow1 = mn1;
        lsum2 = lsum2 * al2 + sum2; mrow2 = mn2;
        #pragma unroll
        for (int j = 0; j < 8; j++) {
            ctx[j][0] *= al1; ctx[j][1] *= al1;
            ctx[j][2] *= al2; ctx[j][3] *= al2;
        }

        // ---- ctx += P V (P in registers, 3-term split) ----
        #pragma unroll
        for (int kg = 0; kg < 8; kg++) {
            uint32_t ah[4], alr[4];
            bsplit2(S[2 * kg][0],     S[2 * kg][1],     ah[0], alr[0]);
            bsplit2(S[2 * kg][2],     S[2 * kg][3],     ah[1], alr[1]);
            bsplit2(S[2 * kg + 1][0], S[2 * kg + 1][1], ah[2], alr[2]);
            bsplit2(S[2 * kg + 1][2], S[2 * kg + 1][3], ah[3], alr[3]);
            #pragma unroll
            for (int pj = 0; pj < 4; pj++) {
                const uint32_t off = (uint32_t)((pj * 16 + b_r) * VSTR + kg * 16 + b_c) * 2;
                uint32_t bh4[4], bl4[4];
                ldsm4(bh4, vhb + off);
                ldsm4(bl4, vlb + off);
                mma16816(ctx[2 * pj],     ah,  &bh4[0]);
                mma16816(ctx[2 * pj],     alr, &bh4[0]);
                mma16816(ctx[2 * pj],     ah,  &bl4[0]);
                mma16816(ctx[2 * pj + 1], ah,  &bh4[2]);
                mma16816(ctx[2 * pj + 1], alr, &bh4[2]);
                mma16816(ctx[2 * pj + 1], ah,  &bl4[2]);
            }
        }
        __syncthreads();
    }

    // ---- tail tiles: fully causal-masked scores fill ----
    {
        const int r = tid >> 1, ch0 = (tid & 1) * 64;
        for (int kt2 = qt + 1; kt2 < 16; kt2++) {
            const int k0 = kt2 * 128;
            #pragma unroll
            for (int i = 0; i < 16; i++) {
                const int cc = ch0 + i * 4;
                const float4 a4 = *(const float4*)(amk + k0 + cc);
                const float4 val = make_float4(-10000.f + a4.x * -10000.f,
                                               -10000.f + a4.y * -10000.f,
                                               -10000.f + a4.z * -10000.f,
                                               -10000.f + a4.w * -10000.f);
                *(float4*)(sc + (size_t)r * SS + k0 + cc) = val;
            }
        }
    }

    // ---- ctx /= lsum -> bf16 hi/lo ----
    const float inv1 = 1.0f / lsum1, inv2 = 1.0f / lsum2;
    #pragma unroll
    for (int j = 0; j < 8; j++) {
        const int d = hq * 64 + j * 8 + colb;
        const size_t o1 = ((size_t)(bb * SS) + q0 + rt1) * HH + d;
        const size_t o2 = ((size_t)(bb * SS) + q0 + rt2) * HH + d;
        uint32_t hi, lo;
        bsplit2(ctx[j][0] * inv1, ctx[j][1] * inv1, hi, lo);
        *(uint32_t*)(g_ch + o1) = hi;
        *(uint32_t*)(g_cl + o1) = lo;
        bsplit2(ctx[j][2] * inv2, ctx[j][3] * inv2, hi, lo);
        *(uint32_t*)(g_ch + o2) = hi;
        *(uint32_t*)(g_cl + o2) = lo;
    }
}

// ---------------- launch ----------------
extern "C" void kernel_launch(void* const* d_in, const int* in_sizes, int n_in,
                              void* d_out, int out_size) {
    const float* hs       = (const float*)d_in[0];
    const float* amask    = (const float*)d_in[1];
    const float* c_attn_w = (const float*)d_in[2];
    const float* c_attn_b = (const float*)d_in[3];
    const float* c_proj_w = (const float*)d_in[4];
    const float* c_proj_b = (const float*)d_in[5];
    const float* ln_g     = (const float*)d_in[6];
    const float* ln_b     = (const float*)d_in[7];
    float* out = (float*)d_out;
    float* scores = out + (size_t)MM * HH;

    __nv_bfloat16 *xh, *xl, *wqh, *wql, *wph, *wpl, *ch, *cl;
    cudaGetSymbolAddress((void**)&xh,  g_xh);
    cudaGetSymbolAddress((void**)&xl,  g_xl);
    cudaGetSymbolAddress((void**)&wqh, g_wqh);
    cudaGetSymbolAddress((void**)&wql, g_wql);
    cudaGetSymbolAddress((void**)&wph, g_wph);
    cudaGetSymbolAddress((void**)&wpl, g_wpl);
    cudaGetSymbolAddress((void**)&ch,  g_ch);
    cudaGetSymbolAddress((void**)&cl,  g_cl);

    cudaFuncSetAttribute(mma_gemm_kernel<0>, cudaFuncAttributeMaxDynamicSharedMemorySize, MMA_SMEM);
    cudaFuncSetAttribute(mma_gemm_kernel<1>, cudaFuncAttributeMaxDynamicSharedMemorySize, MMA_SMEM);
    cudaFuncSetAttribute(attn_mma_kernel, cudaFuncAttributeMaxDynamicSharedMemorySize, ATTN2_SMEM);

    ln_kernel<<<MM, 256>>>(hs, ln_g, ln_b);
    wsplit_kernel<<<dim3(N3 / 32, KK / 32), 256>>>(c_attn_w, wqh, wql, N3);
    wsplit_kernel<<<dim3(HH / 32, KK / 32), 256>>>(c_proj_w, wph, wpl, HH);
    mma_gemm_kernel<0><<<dim3(N3 / 128, MM / 128), 256, MMA_SMEM>>>(
        xh, xl, wqh, wql, c_attn_b, nullptr, nullptr);
    vtrans_kernel<<<dim3(SS / 32, HDD / 32, BB * NHH), 256>>>();
    attn_mma_kernel<<<dim3(16, NHH, BB), 256, ATTN2_SMEM>>>(amask, scores);
    mma_gemm_kernel<1><<<dim3(HH / 128, MM / 128), 256, MMA_SMEM>>>(
        ch, cl, wph, wpl, c_proj_b, hs, out);
}